// round 14
// baseline (speedup 1.0000x reference)
#include <cuda_runtime.h>
#include <cuda_bf16.h>
#include <math.h>

#define BATCH 8192
#define PROTO 4096
#define DIM   1024
#define HEADS 16
#define DH    64
#define KSEL  6

typedef unsigned long long ull;
typedef unsigned int u32;

// ---------------- device scratch ----------------
__device__ float g_bqc[DIM];
__device__ float g_bkc[DIM];
__device__ float g_bvc[DIM];
__device__ float g_qh[BATCH * DIM];
__device__ float g_Kb[PROTO * DIM];
__device__ float g_Vb[PROTO * DIM];
__device__ int   g_topk[BATCH * KSEL];

__device__ __align__(16) __nv_bfloat16 g_q_hi[BATCH * DIM];
__device__ __align__(16) __nv_bfloat16 g_q_lo[BATCH * DIM];
__device__ __align__(16) __nv_bfloat16 g_bank_hi[PROTO * DIM];
__device__ __align__(16) __nv_bfloat16 g_bank_lo[PROTO * DIM];
__device__ __align__(16) __nv_bfloat16 g_ctx_hi[BATCH * DIM];
__device__ __align__(16) __nv_bfloat16 g_ctx_lo[BATCH * DIM];
__device__ __align__(16) __nv_bfloat16 g_Wq_hi[DIM * DIM];
__device__ __align__(16) __nv_bfloat16 g_Wq_lo[DIM * DIM];
__device__ __align__(16) __nv_bfloat16 g_Wk_hi[DIM * DIM];
__device__ __align__(16) __nv_bfloat16 g_Wk_lo[DIM * DIM];
__device__ __align__(16) __nv_bfloat16 g_Wv_hi[DIM * DIM];
__device__ __align__(16) __nv_bfloat16 g_Wv_lo[DIM * DIM];
__device__ __align__(16) __nv_bfloat16 g_WqpT_hi[DIM * DIM];
__device__ __align__(16) __nv_bfloat16 g_WqpT_lo[DIM * DIM];
__device__ __align__(16) __nv_bfloat16 g_WppT_hi[DIM * DIM];
__device__ __align__(16) __nv_bfloat16 g_WppT_lo[DIM * DIM];
__device__ __align__(16) __nv_bfloat16 g_Wqc_hi[DIM * DIM];
__device__ __align__(16) __nv_bfloat16 g_Wqc_lo[DIM * DIM];
__device__ __align__(16) __nv_bfloat16 g_Wkc_hi[DIM * DIM];
__device__ __align__(16) __nv_bfloat16 g_Wkc_lo[DIM * DIM];
__device__ __align__(16) __nv_bfloat16 g_Wvc_hi[DIM * DIM];
__device__ __align__(16) __nv_bfloat16 g_Wvc_lo[DIM * DIM];
__device__ __align__(16) __nv_bfloat16 g_Wo_hi[DIM * DIM];
__device__ __align__(16) __nv_bfloat16 g_Wo_lo[DIM * DIM];

// ---------------- low-level helpers ----------------
__device__ __forceinline__ u32 smem_u32(const void* p) {
    u32 a;
    asm("{ .reg .u64 t; cvta.to.shared.u64 t, %1; cvt.u32.u64 %0, t; }"
        : "=r"(a) : "l"(p));
    return a;
}
__device__ __forceinline__ void cp_async16(u32 dst, const void* src) {
    asm volatile("cp.async.cg.shared.global [%0], [%1], 16;"
                 :: "r"(dst), "l"(src) : "memory");
}
__device__ __forceinline__ void cp_commit() {
    asm volatile("cp.async.commit_group;" ::: "memory");
}
__device__ __forceinline__ void cp_wait0() {
    asm volatile("cp.async.wait_group 0;" ::: "memory");
}
__device__ __forceinline__ void ldsm4(u32* d, u32 addr) {
    asm volatile("ldmatrix.sync.aligned.m8n8.x4.shared.b16 {%0,%1,%2,%3}, [%4];"
                 : "=r"(d[0]), "=r"(d[1]), "=r"(d[2]), "=r"(d[3]) : "r"(addr));
}
__device__ __forceinline__ void mma_bf16(float* c, const u32* a, u32 b0, u32 b1) {
    asm volatile("mma.sync.aligned.m16n8k16.row.col.f32.bf16.bf16.f32 "
                 "{%0,%1,%2,%3},{%4,%5,%6,%7},{%8,%9},{%0,%1,%2,%3};"
                 : "+f"(c[0]), "+f"(c[1]), "+f"(c[2]), "+f"(c[3])
                 : "r"(a[0]), "r"(a[1]), "r"(a[2]), "r"(a[3]), "r"(b0), "r"(b1));
}
__device__ __forceinline__ u32 pack_bf16(float x, float y) {
    __nv_bfloat162 p = __floats2bfloat162_rn(x, y);
    return *(u32*)&p;
}

// ---------------- fused prep: splits + bias combines + topk ---------------
struct PrepAll {
    const float* X[6];
    __nv_bfloat16* hi[6];
    __nv_bfloat16* lo[6];
    int prefix[6];
    const float* W[3];
    const float* bin[3];
    const float* badd[3];
    float* bout[3];
    const float* logits;
    int* topk;
};

__device__ __forceinline__ void topk6_body(const float* __restrict__ src,
                                           int* __restrict__ out) {
    const int tid = threadIdx.x;   // 256
    const int lane = tid & 31, wid = tid >> 5;

    float v[KSEL]; int ix[KSEL];
    #pragma unroll
    for (int q = 0; q < KSEL; q++) { v[q] = -INFINITY; ix[q] = 0x7fffffff; }

    #pragma unroll
    for (int pp = 0; pp < PROTO / 256 / 4; pp++) {
        int i = (tid + pp * 256) * 4;
        float4 x4 = *(const float4*)(src + i);
        float xs[4] = {x4.x, x4.y, x4.z, x4.w};
        #pragma unroll
        for (int u = 0; u < 4; u++) {
            float x = xs[u];
            if (x > v[KSEL - 1]) {
                v[KSEL - 1] = x; ix[KSEL - 1] = i + u;
                #pragma unroll
                for (int q = KSEL - 1; q > 0; q--) {
                    if (v[q] > v[q - 1]) {
                        float tv = v[q]; v[q] = v[q - 1]; v[q - 1] = tv;
                        int ti = ix[q]; ix[q] = ix[q - 1]; ix[q - 1] = ti;
                    }
                }
            }
        }
    }

    __shared__ float wv[8][KSEL];
    __shared__ int   wi[8][KSEL];
    #pragma unroll
    for (int t = 0; t < KSEL; t++) {
        float cv = v[0]; int ci = ix[0];
        #pragma unroll
        for (int o = 16; o; o >>= 1) {
            float ov = __shfl_down_sync(0xffffffffu, cv, o);
            int oi = __shfl_down_sync(0xffffffffu, ci, o);
            if (ov > cv || (ov == cv && oi < ci)) { cv = ov; ci = oi; }
        }
        cv = __shfl_sync(0xffffffffu, cv, 0);
        ci = __shfl_sync(0xffffffffu, ci, 0);
        if (lane == 0) { wv[wid][t] = cv; wi[wid][t] = ci; }
        if (ix[0] == ci) {
            #pragma unroll
            for (int q = 0; q < KSEL - 1; q++) { v[q] = v[q + 1]; ix[q] = ix[q + 1]; }
            v[KSEL - 1] = -INFINITY; ix[KSEL - 1] = 0x7fffffff;
        }
    }
    __syncthreads();

    if (wid == 0) {
        float lv[KSEL]; int li[KSEL];
        #pragma unroll
        for (int q = 0; q < KSEL; q++) {
            lv[q] = (lane < 8) ? wv[lane][q] : -INFINITY;
            li[q] = (lane < 8) ? wi[lane][q] : 0x7fffffff;
        }
        #pragma unroll
        for (int t = 0; t < KSEL; t++) {
            float cv = lv[0]; int ci = li[0];
            #pragma unroll
            for (int o = 16; o; o >>= 1) {
                float ov = __shfl_down_sync(0xffffffffu, cv, o);
                int oi = __shfl_down_sync(0xffffffffu, ci, o);
                if (ov > cv || (ov == cv && oi < ci)) { cv = ov; ci = oi; }
            }
            cv = __shfl_sync(0xffffffffu, cv, 0);
            ci = __shfl_sync(0xffffffffu, ci, 0);
            if (lane == 0) out[t] = ci;
            if (li[0] == ci) {
                #pragma unroll
                for (int q = 0; q < KSEL - 1; q++) { lv[q] = lv[q + 1]; li[q] = li[q + 1]; }
                lv[KSEL - 1] = -INFINITY; li[KSEL - 1] = 0x7fffffff;
            }
        }
    }
}

__global__ void prep_kernel(PrepAll p) {
    const int bid = blockIdx.x;
    if (bid < 8192) {
        int z = 0;
        #pragma unroll
        for (int q = 1; q < 6; q++) if (bid >= p.prefix[q]) z = q;
        size_t id = (((size_t)(bid - p.prefix[z])) * 256 + threadIdx.x) * 8;
        const float4* src = (const float4*)(p.X[z] + id);
        float4 a = src[0], b = src[1];
        float xs[8] = {a.x, a.y, a.z, a.w, b.x, b.y, b.z, b.w};
        __nv_bfloat16 h[8], l[8];
        #pragma unroll
        for (int i = 0; i < 8; i++) {
            h[i] = __float2bfloat16(xs[i]);
            l[i] = __float2bfloat16(xs[i] - __bfloat162float(h[i]));
        }
        *(uint4*)(p.hi[z] + id) = *(uint4*)h;
        *(uint4*)(p.lo[z] + id) = *(uint4*)l;
    } else if (bid < 8576) {
        const int r = bid - 8192;
        const int z = r >> 7;
        const int warp = threadIdx.x >> 5, lane = threadIdx.x & 31;
        const int i = (r & 127) * 8 + warp;
        const float* __restrict__ row = p.W[z] + (size_t)i * DIM;
        const float* __restrict__ bin = p.bin[z];
        float s = 0.0f;
        for (int t = lane; t < DIM; t += 32) s = fmaf(row[t], bin[t], s);
        #pragma unroll
        for (int o = 16; o; o >>= 1) s += __shfl_down_sync(0xffffffffu, s, o);
        if (lane == 0) p.bout[z][i] = s + p.badd[z][i];
    } else {
        const int b = bid - 8576;
        topk6_body(p.logits + (size_t)b * PROTO, p.topk + (size_t)b * KSEL);
    }
}

// ---------------- transpose-split ----------------
struct TSplit2 {
    const float* X[2];
    __nv_bfloat16* hi[2];
    __nv_bfloat16* lo[2];
};
__global__ void tsplit_kernel(TSplit2 p) {
    __shared__ float t[32][33];
    const int z = blockIdx.z;
    const float* __restrict__ X = p.X[z];
    const int tx = threadIdx.x & 31, ty = threadIdx.x >> 5;
    const int bx = blockIdx.x * 32, by = blockIdx.y * 32;
    #pragma unroll
    for (int i = 0; i < 4; i++)
        t[ty + 8 * i][tx] = X[(size_t)(by + ty + 8 * i) * DIM + bx + tx];
    __syncthreads();
    #pragma unroll
    for (int i = 0; i < 4; i++) {
        float x = t[tx][ty + 8 * i];
        __nv_bfloat16 h = __float2bfloat16(x);
        __nv_bfloat16 l = __float2bfloat16(x - __bfloat162float(h));
        size_t o = (size_t)(bx + ty + 8 * i) * DIM + by + tx;
        p.hi[z][o] = h;
        p.lo[z][o] = l;
    }
}

// ---------------- mma.sync GEMM (bf16x3), 128x128 tile, 2 CTAs/SM ---------
// 512 threads, 16 warps 4m x 4n => warp tile 32x32. 2-stage cp.async.
#define BK 32
#define SKB2 80                       /* smem row stride bytes */
#define TILE_SM2 (128 * SKB2)         /* 10240 B, all 4 tiles equal */
#define STAGE_SM (4 * TILE_SM2)       /* 40960 B */
#define MMA_SMEM (2 * STAGE_SM)       /* 81920 B -> 2 CTAs/SM */
#define NTILES (DIM / 128)            /* 8 n-tiles per row block */

struct MmaJob {
    const __nv_bfloat16 *Ahi, *Alo, *Bhi, *Blo;
    const float* bias;
    float* C;
    __nv_bfloat16 *Chi, *Clo;
    int prefix;
};
struct MmaB {
    MmaJob j[3];
    int nj;
};

__global__ __launch_bounds__(512, 2)
void mma_gemm(MmaB p) {
    extern __shared__ __align__(16) char sm[];
    const u32 sbase = smem_u32(sm);

    const int bid = blockIdx.x;
    int z = 0;
    if (p.nj > 1 && bid >= p.j[1].prefix) z = 1;
    if (p.nj > 2 && bid >= p.j[2].prefix) z = 2;
    const MmaJob& J = p.j[z];
    const int rel = bid - J.prefix;
    const int m0 = (rel / NTILES) * 128, n0 = (rel % NTILES) * 128;

    const int tid = threadIdx.x, lane = tid & 31, wid = tid >> 5;
    const int wm = wid >> 2, wn = wid & 3;   // 4x4 warps, 32x32 warp tile

    // loads: 1 x 16B chunk per thread per tile (4 tiles)
    const int lrow = tid >> 2, lseg = tid & 3;
    const __nv_bfloat16* gAhi = J.Ahi + (size_t)(m0 + lrow) * DIM + lseg * 8;
    const __nv_bfloat16* gAlo = J.Alo + (size_t)(m0 + lrow) * DIM + lseg * 8;
    const __nv_bfloat16* gBhi = J.Bhi + (size_t)(n0 + lrow) * DIM + lseg * 8;
    const __nv_bfloat16* gBlo = J.Blo + (size_t)(n0 + lrow) * DIM + lseg * 8;
    const u32 dT = lrow * SKB2 + lseg * 16;

    auto load_stage = [&](int s) {
        const u32 st_ = sbase + (s & 1) * STAGE_SM;
        const int k0_ = s * BK;
        cp_async16(st_ + dT,                gAhi + k0_);
        cp_async16(st_ + TILE_SM2 + dT,     gAlo + k0_);
        cp_async16(st_ + 2 * TILE_SM2 + dT, gBhi + k0_);
        cp_async16(st_ + 3 * TILE_SM2 + dT, gBlo + k0_);
        cp_commit();
    };

    float c[2][4][4];
    #pragma unroll
    for (int i = 0; i < 2; i++)
        #pragma unroll
        for (int j = 0; j < 4; j++)
            #pragma unroll
            for (int q = 0; q < 4; q++) c[i][j][q] = 0.0f;

    const int NS = DIM / BK;   // 32
    load_stage(0);

    const u32 rowoff = (lane & 15) * SKB2 + (lane >> 4) * 16;

    for (int s = 0; s < NS; s++) {
        cp_wait0();
        __syncthreads();          // stage s visible; stage s-1 fully consumed
        if (s + 1 < NS) load_stage(s + 1);

        const u32 st = sbase + (s & 1) * STAGE_SM;
        const u32 aHiB = st + (wm * 32) * SKB2 + rowoff;
        const u32 aLoB = aHiB + TILE_SM2;
        const u32 bHiB = st + 2 * TILE_SM2 + (wn * 32) * SKB2 + rowoff;
        const u32 bLoB = bHiB + TILE_SM2;

        #pragma unroll
        for (int kk = 0; kk < 2; kk++) {
            const u32 ko = kk * 32;
            u32 ah[2][4], al[2][4];
            ldsm4(ah[0], aHiB + ko);
            ldsm4(ah[1], aHiB + 16 * SKB2 + ko);
            ldsm4(al[0], aLoB + ko);
            ldsm4(al[1], aLoB + 16 * SKB2 + ko);
            #pragma unroll
            for (int g = 0; g < 2; g++) {
                u32 bh[4], bl[4];
                ldsm4(bh, bHiB + g * 16 * SKB2 + ko);
                ldsm4(bl, bLoB + g * 16 * SKB2 + ko);
                #pragma unroll
                for (int mi = 0; mi < 2; mi++)
                    #pragma unroll
                    for (int sub = 0; sub < 2; sub++) {
                        float* cc = c[mi][g * 2 + sub];
                        mma_bf16(cc, ah[mi], bh[sub], bh[sub + 2]);
                        mma_bf16(cc, ah[mi], bl[sub], bl[sub + 2]);
                        mma_bf16(cc, al[mi], bh[sub], bh[sub + 2]);
                    }
            }
        }
    }

    // epilogue
    if (J.C) {
        float* __restrict__ C = J.C;
        const float* __restrict__ bias = J.bias;
        #pragma unroll
        for (int mi = 0; mi < 2; mi++) {
            const int row = m0 + wm * 32 + mi * 16 + (lane >> 2);
            #pragma unroll
            for (int ni = 0; ni < 4; ni++) {
                const int col = n0 + wn * 32 + ni * 8 + 2 * (lane & 3);
                float2 bv = bias ? *(const float2*)(bias + col)
                                 : make_float2(0.0f, 0.0f);
                const float* cc = c[mi][ni];
                *(float2*)&C[(size_t)row * DIM + col] =
                    make_float2(cc[0] + bv.x, cc[1] + bv.y);
                *(float2*)&C[(size_t)(row + 8) * DIM + col] =
                    make_float2(cc[2] + bv.x, cc[3] + bv.y);
            }
        }
    } else {
        __nv_bfloat16* __restrict__ Chi = J.Chi;
        __nv_bfloat16* __restrict__ Clo = J.Clo;
        #pragma unroll
        for (int mi = 0; mi < 2; mi++) {
            const int row = m0 + wm * 32 + mi * 16 + (lane >> 2);
            #pragma unroll
            for (int ni = 0; ni < 4; ni++) {
                const int col = n0 + wn * 32 + ni * 8 + 2 * (lane & 3);
                const float* cc = c[mi][ni];
                #pragma unroll
                for (int rr = 0; rr < 2; rr++) {
                    float x0 = cc[rr * 2], x1 = cc[rr * 2 + 1];
                    __nv_bfloat16 h0 = __float2bfloat16(x0);
                    __nv_bfloat16 h1 = __float2bfloat16(x1);
                    float l0 = x0 - __bfloat162float(h0);
                    float l1 = x1 - __bfloat162float(h1);
                    size_t o = (size_t)(row + rr * 8) * DIM + col;
                    __nv_bfloat162 hp; hp.x = h0; hp.y = h1;
                    *(u32*)&Chi[o] = *(u32*)&hp;
                    *(u32*)&Clo[o] = pack_bf16(l0, l1);
                }
            }
        }
    }
}

// ---------------- per-row attention, 256 threads ---------------------------
__global__ void attention_kernel(const float* __restrict__ qh,
                                 const float* __restrict__ Kb,
                                 const float* __restrict__ Vb,
                                 const int* __restrict__ topk,
                                 __nv_bfloat16* __restrict__ ctx_hi,
                                 __nv_bfloat16* __restrict__ ctx_lo,
                                 float* __restrict__ attn_out) {
    const int b = blockIdx.x;
    const int tid = threadIdx.x;   // 256
    __shared__ float q_s[DIM];
    __shared__ float k_s[KSEL][DIM];
    __shared__ int   idx_s[KSEL];
    __shared__ float s_s[HEADS][KSEL];

    if (tid < KSEL) idx_s[tid] = topk[(size_t)b * KSEL + tid];
    __syncthreads();

    {
        const float4* q4 = (const float4*)(qh + (size_t)b * DIM);
        float4* qs4 = (float4*)q_s;
        qs4[tid] = q4[tid];
        #pragma unroll
        for (int j = 0; j < KSEL; j++) {
            ((float4*)k_s[j])[tid] =
                ((const float4*)(Kb + (size_t)idx_s[j] * DIM))[tid];
        }
    }
    __syncthreads();

    if (tid < HEADS * KSEL) {
        int h = tid / KSEL, j = tid % KSEL;
        float dot = 0.0f;
        #pragma unroll
        for (int d = 0; d < DH; d++)
            dot = fmaf(q_s[h * DH + d], k_s[j][h * DH + d], dot);
        s_s[h][j] = dot * 0.125f;
    }
    __syncthreads();

    if (tid < HEADS) {
        int h = tid;
        float m = s_s[h][0];
        #pragma unroll
        for (int j = 1; j < KSEL; j++) m = fmaxf(m, s_s[h][j]);
        float e[KSEL], sum = 0.0f;
        #pragma unroll
        for (int j = 0; j < KSEL; j++) { e[j] = expf(s_s[h][j] - m); sum += e[j]; }
        float inv = 1.0f / sum;
        #pragma unroll
        for (int j = 0; j < KSEL; j++) s_s[h][j] = e[j] * inv;
    }
    __syncthreads();

    if (tid < KSEL) {
        float m = 0.0f;
        #pragma unroll
        for (int h = 0; h < HEADS; h++) m += s_s[h][tid];
        attn_out[(size_t)b * KSEL + tid] = m * (1.0f / HEADS);
    }

    #pragma unroll
    for (int it = 0; it < DIM / 256; it++) {
        int d = tid + it * 256;
        int h = d / DH;
        float acc = 0.0f;
        #pragma unroll
        for (int j = 0; j < KSEL; j++)
            acc = fmaf(s_s[h][j], Vb[(size_t)idx_s[j] * DIM + d], acc);
        __nv_bfloat16 hh = __float2bfloat16(acc);
        ctx_hi[(size_t)b * DIM + d] = hh;
        ctx_lo[(size_t)b * DIM + d] =
            __float2bfloat16(acc - __bfloat162float(hh));
    }
}

// ---------------- host launcher -------------------------------------------
extern "C" void kernel_launch(void* const* d_in, const int* in_sizes, int n_in,
                              void* d_out, int out_size) {
    const float* query  = (const float*)d_in[0];
    const float* bank   = (const float*)d_in[1];
    const float* logits = (const float*)d_in[2];
    const float* Wq_proj = (const float*)d_in[3];
    const float* bq_proj = (const float*)d_in[4];
    const float* Wp_proj = (const float*)d_in[5];
    const float* bp_proj = (const float*)d_in[6];
    const float* Wq = (const float*)d_in[7];
    const float* bq = (const float*)d_in[8];
    const float* Wk = (const float*)d_in[9];
    const float* bk = (const float*)d_in[10];
    const float* Wv = (const float*)d_in[11];
    const float* bv = (const float*)d_in[12];
    const float* Wo = (const float*)d_in[13];
    const float* bo = (const float*)d_in[14];

    float* out = (float*)d_out;
    float* out_ctx  = out;
    float* out_attn = out + (size_t)BATCH * DIM;

    float *bqc, *bkc, *bvc, *qh, *Kb, *Vb;
    int* topk;
    cudaGetSymbolAddress((void**)&bqc, g_bqc);
    cudaGetSymbolAddress((void**)&bkc, g_bkc);
    cudaGetSymbolAddress((void**)&bvc, g_bvc);
    cudaGetSymbolAddress((void**)&qh,  g_qh);
    cudaGetSymbolAddress((void**)&Kb,  g_Kb);
    cudaGetSymbolAddress((void**)&Vb,  g_Vb);
    cudaGetSymbolAddress((void**)&topk, g_topk);

    __nv_bfloat16 *q_hi, *q_lo, *bank_hi, *bank_lo, *ctx_hi, *ctx_lo;
    __nv_bfloat16 *Wq_hi, *Wq_lo, *Wk_hi, *Wk_lo, *Wv_hi, *Wv_lo;
    __nv_bfloat16 *WqpT_hi, *WqpT_lo, *WppT_hi, *WppT_lo;
    __nv_bfloat16 *Wqc_hi, *Wqc_lo, *Wkc_hi, *Wkc_lo, *Wvc_hi, *Wvc_lo, *Wo_hi, *Wo_lo;
    cudaGetSymbolAddress((void**)&q_hi, g_q_hi);
    cudaGetSymbolAddress((void**)&q_lo, g_q_lo);
    cudaGetSymbolAddress((void**)&bank_hi, g_bank_hi);
    cudaGetSymbolAddress((void**)&bank_lo, g_bank_lo);
    cudaGetSymbolAddress((void**)&ctx_hi, g_ctx_hi);
    cudaGetSymbolAddress((void**)&ctx_lo, g_ctx_lo);
    cudaGetSymbolAddress((void**)&Wq_hi, g_Wq_hi);
    cudaGetSymbolAddress((void**)&Wq_lo, g_Wq_lo);
    cudaGetSymbolAddress((void**)&Wk_hi, g_Wk_hi);
    cudaGetSymbolAddress((void**)&Wk_lo, g_Wk_lo);
    cudaGetSymbolAddress((void**)&Wv_hi, g_Wv_hi);
    cudaGetSymbolAddress((void**)&Wv_lo, g_Wv_lo);
    cudaGetSymbolAddress((void**)&WqpT_hi, g_WqpT_hi);
    cudaGetSymbolAddress((void**)&WqpT_lo, g_WqpT_lo);
    cudaGetSymbolAddress((void**)&WppT_hi, g_WppT_hi);
    cudaGetSymbolAddress((void**)&WppT_lo, g_WppT_lo);
    cudaGetSymbolAddress((void**)&Wqc_hi, g_Wqc_hi);
    cudaGetSymbolAddress((void**)&Wqc_lo, g_Wqc_lo);
    cudaGetSymbolAddress((void**)&Wkc_hi, g_Wkc_hi);
    cudaGetSymbolAddress((void**)&Wkc_lo, g_Wkc_lo);
    cudaGetSymbolAddress((void**)&Wvc_hi, g_Wvc_hi);
    cudaGetSymbolAddress((void**)&Wvc_lo, g_Wvc_lo);
    cudaGetSymbolAddress((void**)&Wo_hi, g_Wo_hi);
    cudaGetSymbolAddress((void**)&Wo_lo, g_Wo_lo);

    cudaFuncSetAttribute(mma_gemm,
                         cudaFuncAttributeMaxDynamicSharedMemorySize, MMA_SMEM);

    // #1 fused prep: row-splits + bias combines + topk
    {
        PrepAll s = {};
        s.X[0] = query; s.hi[0] = q_hi;    s.lo[0] = q_lo;    s.prefix[0] = 0;
        s.X[1] = bank;  s.hi[1] = bank_hi; s.lo[1] = bank_lo; s.prefix[1] = 4096;
        s.X[2] = Wo;    s.hi[2] = Wo_hi;   s.lo[2] = Wo_lo;   s.prefix[2] = 6144;
        s.X[3] = Wq;    s.hi[3] = Wq_hi;   s.lo[3] = Wq_lo;   s.prefix[3] = 6656;
        s.X[4] = Wk;    s.hi[4] = Wk_hi;   s.lo[4] = Wk_lo;   s.prefix[4] = 7168;
        s.X[5] = Wv;    s.hi[5] = Wv_hi;   s.lo[5] = Wv_lo;   s.prefix[5] = 7680;
        s.W[0] = Wq; s.bin[0] = bq_proj; s.badd[0] = bq; s.bout[0] = bqc;
        s.W[1] = Wk; s.bin[1] = bp_proj; s.badd[1] = bk; s.bout[1] = bkc;
        s.W[2] = Wv; s.bin[2] = bp_proj; s.badd[2] = bv; s.bout[2] = bvc;
        s.logits = logits; s.topk = topk;
        prep_kernel<<<16768, 256>>>(s);
    }

    // #2 transpose-splits of projection weights
    {
        TSplit2 t = {};
        t.X[0] = Wq_proj; t.X[1] = Wp_proj;
        t.hi[0] = WqpT_hi; t.hi[1] = WppT_hi;
        t.lo[0] = WqpT_lo; t.lo[1] = WppT_lo;
        tsplit_kernel<<<dim3(32, 32, 2), 256>>>(t);
    }

    // #3 weight combines: 3 x 64 = 192 blocks (one wave)
    {
        MmaB mb = {};
        mb.nj = 3;
        mb.j[0] = {Wq_hi, Wq_lo, WqpT_hi, WqpT_lo, nullptr, nullptr,
                   Wqc_hi, Wqc_lo, 0};
        mb.j[1] = {Wk_hi, Wk_lo, WppT_hi, WppT_lo, nullptr, nullptr,
                   Wkc_hi, Wkc_lo, 64};
        mb.j[2] = {Wv_hi, Wv_lo, WppT_hi, WppT_lo, nullptr, nullptr,
                   Wvc_hi, Wvc_lo, 128};
        mma_gemm<<<192, 512, MMA_SMEM>>>(mb);
    }

    // #4 merged big GEMMs: qh (512), Kb (256), Vb (256)  [ncu lands here]
    {
        MmaB mb = {};
        mb.nj = 3;
        mb.j[0] = {q_hi, q_lo, Wqc_hi, Wqc_lo, bqc, qh, nullptr, nullptr, 0};
        mb.j[1] = {bank_hi, bank_lo, Wkc_hi, Wkc_lo, bkc, Kb, nullptr, nullptr, 512};
        mb.j[2] = {bank_hi, bank_lo, Wvc_hi, Wvc_lo, bvc, Vb, nullptr, nullptr, 768};
        mma_gemm<<<1024, 512, MMA_SMEM>>>(mb);
    }

    // #5 attention
    attention_kernel<<<BATCH, 256>>>(qh, Kb, Vb, topk, ctx_hi, ctx_lo, out_attn);

    // #6 out projection (512 blocks)
    {
        MmaB mb = {};
        mb.nj = 1;
        mb.j[0] = {ctx_hi, ctx_lo, Wo_hi, Wo_lo, bo, out_ctx, nullptr, nullptr, 0};
        mma_gemm<<<512, 512, MMA_SMEM>>>(mb);
    }
}

// round 15
// speedup vs baseline: 1.0256x; 1.0256x over previous
#include <cuda_runtime.h>
#include <cuda_bf16.h>
#include <math.h>

#define BATCH 8192
#define PROTO 4096
#define DIM   1024
#define HEADS 16
#define DH    64
#define KSEL  6

typedef unsigned long long ull;
typedef unsigned int u32;

// ---------------- device scratch ----------------
__device__ float g_bqc[DIM];
__device__ float g_bkc[DIM];
__device__ float g_bvc[DIM];
__device__ float g_qh[BATCH * DIM];
__device__ float g_Kb[PROTO * DIM];
__device__ float g_Vb[PROTO * DIM];
__device__ int   g_topk[BATCH * KSEL];

__device__ __align__(16) __nv_bfloat16 g_q_hi[BATCH * DIM];
__device__ __align__(16) __nv_bfloat16 g_q_lo[BATCH * DIM];
__device__ __align__(16) __nv_bfloat16 g_bank_hi[PROTO * DIM];
__device__ __align__(16) __nv_bfloat16 g_bank_lo[PROTO * DIM];
__device__ __align__(16) __nv_bfloat16 g_ctx_hi[BATCH * DIM];
__device__ __align__(16) __nv_bfloat16 g_ctx_lo[BATCH * DIM];
__device__ __align__(16) __nv_bfloat16 g_Wq_hi[DIM * DIM];
__device__ __align__(16) __nv_bfloat16 g_Wq_lo[DIM * DIM];
__device__ __align__(16) __nv_bfloat16 g_Wk_hi[DIM * DIM];
__device__ __align__(16) __nv_bfloat16 g_Wk_lo[DIM * DIM];
__device__ __align__(16) __nv_bfloat16 g_Wv_hi[DIM * DIM];
__device__ __align__(16) __nv_bfloat16 g_Wv_lo[DIM * DIM];
__device__ __align__(16) __nv_bfloat16 g_WqpT_hi[DIM * DIM];
__device__ __align__(16) __nv_bfloat16 g_WqpT_lo[DIM * DIM];
__device__ __align__(16) __nv_bfloat16 g_WppT_hi[DIM * DIM];
__device__ __align__(16) __nv_bfloat16 g_WppT_lo[DIM * DIM];
__device__ __align__(16) __nv_bfloat16 g_Wqc_hi[DIM * DIM];
__device__ __align__(16) __nv_bfloat16 g_Wqc_lo[DIM * DIM];
__device__ __align__(16) __nv_bfloat16 g_Wkc_hi[DIM * DIM];
__device__ __align__(16) __nv_bfloat16 g_Wkc_lo[DIM * DIM];
__device__ __align__(16) __nv_bfloat16 g_Wvc_hi[DIM * DIM];
__device__ __align__(16) __nv_bfloat16 g_Wvc_lo[DIM * DIM];
__device__ __align__(16) __nv_bfloat16 g_Wo_hi[DIM * DIM];
__device__ __align__(16) __nv_bfloat16 g_Wo_lo[DIM * DIM];

// ---------------- low-level helpers ----------------
__device__ __forceinline__ u32 smem_u32(const void* p) {
    u32 a;
    asm("{ .reg .u64 t; cvta.to.shared.u64 t, %1; cvt.u32.u64 %0, t; }"
        : "=r"(a) : "l"(p));
    return a;
}
__device__ __forceinline__ void cp_async16(u32 dst, const void* src) {
    asm volatile("cp.async.cg.shared.global [%0], [%1], 16;"
                 :: "r"(dst), "l"(src) : "memory");
}
__device__ __forceinline__ void cp_commit() {
    asm volatile("cp.async.commit_group;" ::: "memory");
}
__device__ __forceinline__ void cp_wait1() {
    asm volatile("cp.async.wait_group 1;" ::: "memory");
}
__device__ __forceinline__ void cp_wait0() {
    asm volatile("cp.async.wait_group 0;" ::: "memory");
}
__device__ __forceinline__ void ldsm4(u32* d, u32 addr) {
    asm volatile("ldmatrix.sync.aligned.m8n8.x4.shared.b16 {%0,%1,%2,%3}, [%4];"
                 : "=r"(d[0]), "=r"(d[1]), "=r"(d[2]), "=r"(d[3]) : "r"(addr));
}
__device__ __forceinline__ void mma_bf16(float* c, const u32* a, u32 b0, u32 b1) {
    asm volatile("mma.sync.aligned.m16n8k16.row.col.f32.bf16.bf16.f32 "
                 "{%0,%1,%2,%3},{%4,%5,%6,%7},{%8,%9},{%0,%1,%2,%3};"
                 : "+f"(c[0]), "+f"(c[1]), "+f"(c[2]), "+f"(c[3])
                 : "r"(a[0]), "r"(a[1]), "r"(a[2]), "r"(a[3]), "r"(b0), "r"(b1));
}
__device__ __forceinline__ u32 pack_bf16(float x, float y) {
    __nv_bfloat162 p = __floats2bfloat162_rn(x, y);
    return *(u32*)&p;
}

// ---------------- fused prep: splits + bias combines + topk ---------------
struct PrepAll {
    const float* X[6];
    __nv_bfloat16* hi[6];
    __nv_bfloat16* lo[6];
    int prefix[6];
    const float* W[3];
    const float* bin[3];
    const float* badd[3];
    float* bout[3];
    const float* logits;
    int* topk;
};

__device__ __forceinline__ void topk6_body(const float* __restrict__ src,
                                           int* __restrict__ out) {
    const int tid = threadIdx.x;   // 256
    const int lane = tid & 31, wid = tid >> 5;

    float v[KSEL]; int ix[KSEL];
    #pragma unroll
    for (int q = 0; q < KSEL; q++) { v[q] = -INFINITY; ix[q] = 0x7fffffff; }

    #pragma unroll
    for (int pp = 0; pp < PROTO / 256 / 4; pp++) {
        int i = (tid + pp * 256) * 4;
        float4 x4 = *(const float4*)(src + i);
        float xs[4] = {x4.x, x4.y, x4.z, x4.w};
        #pragma unroll
        for (int u = 0; u < 4; u++) {
            float x = xs[u];
            if (x > v[KSEL - 1]) {
                v[KSEL - 1] = x; ix[KSEL - 1] = i + u;
                #pragma unroll
                for (int q = KSEL - 1; q > 0; q--) {
                    if (v[q] > v[q - 1]) {
                        float tv = v[q]; v[q] = v[q - 1]; v[q - 1] = tv;
                        int ti = ix[q]; ix[q] = ix[q - 1]; ix[q - 1] = ti;
                    }
                }
            }
        }
    }

    __shared__ float wv[8][KSEL];
    __shared__ int   wi[8][KSEL];
    #pragma unroll
    for (int t = 0; t < KSEL; t++) {
        float cv = v[0]; int ci = ix[0];
        #pragma unroll
        for (int o = 16; o; o >>= 1) {
            float ov = __shfl_down_sync(0xffffffffu, cv, o);
            int oi = __shfl_down_sync(0xffffffffu, ci, o);
            if (ov > cv || (ov == cv && oi < ci)) { cv = ov; ci = oi; }
        }
        cv = __shfl_sync(0xffffffffu, cv, 0);
        ci = __shfl_sync(0xffffffffu, ci, 0);
        if (lane == 0) { wv[wid][t] = cv; wi[wid][t] = ci; }
        if (ix[0] == ci) {
            #pragma unroll
            for (int q = 0; q < KSEL - 1; q++) { v[q] = v[q + 1]; ix[q] = ix[q + 1]; }
            v[KSEL - 1] = -INFINITY; ix[KSEL - 1] = 0x7fffffff;
        }
    }
    __syncthreads();

    if (wid == 0) {
        float lv[KSEL]; int li[KSEL];
        #pragma unroll
        for (int q = 0; q < KSEL; q++) {
            lv[q] = (lane < 8) ? wv[lane][q] : -INFINITY;
            li[q] = (lane < 8) ? wi[lane][q] : 0x7fffffff;
        }
        #pragma unroll
        for (int t = 0; t < KSEL; t++) {
            float cv = lv[0]; int ci = li[0];
            #pragma unroll
            for (int o = 16; o; o >>= 1) {
                float ov = __shfl_down_sync(0xffffffffu, cv, o);
                int oi = __shfl_down_sync(0xffffffffu, ci, o);
                if (ov > cv || (ov == cv && oi < ci)) { cv = ov; ci = oi; }
            }
            cv = __shfl_sync(0xffffffffu, cv, 0);
            ci = __shfl_sync(0xffffffffu, ci, 0);
            if (lane == 0) out[t] = ci;
            if (li[0] == ci) {
                #pragma unroll
                for (int q = 0; q < KSEL - 1; q++) { lv[q] = lv[q + 1]; li[q] = li[q + 1]; }
                lv[KSEL - 1] = -INFINITY; li[KSEL - 1] = 0x7fffffff;
            }
        }
    }
}

__global__ void prep_kernel(PrepAll p) {
    const int bid = blockIdx.x;
    if (bid < 8192) {
        int z = 0;
        #pragma unroll
        for (int q = 1; q < 6; q++) if (bid >= p.prefix[q]) z = q;
        size_t id = (((size_t)(bid - p.prefix[z])) * 256 + threadIdx.x) * 8;
        const float4* src = (const float4*)(p.X[z] + id);
        float4 a = src[0], b = src[1];
        float xs[8] = {a.x, a.y, a.z, a.w, b.x, b.y, b.z, b.w};
        __nv_bfloat16 h[8], l[8];
        #pragma unroll
        for (int i = 0; i < 8; i++) {
            h[i] = __float2bfloat16(xs[i]);
            l[i] = __float2bfloat16(xs[i] - __bfloat162float(h[i]));
        }
        *(uint4*)(p.hi[z] + id) = *(uint4*)h;
        *(uint4*)(p.lo[z] + id) = *(uint4*)l;
    } else if (bid < 8576) {
        const int r = bid - 8192;
        const int z = r >> 7;
        const int warp = threadIdx.x >> 5, lane = threadIdx.x & 31;
        const int i = (r & 127) * 8 + warp;
        const float* __restrict__ row = p.W[z] + (size_t)i * DIM;
        const float* __restrict__ bin = p.bin[z];
        float s = 0.0f;
        for (int t = lane; t < DIM; t += 32) s = fmaf(row[t], bin[t], s);
        #pragma unroll
        for (int o = 16; o; o >>= 1) s += __shfl_down_sync(0xffffffffu, s, o);
        if (lane == 0) p.bout[z][i] = s + p.badd[z][i];
    } else {
        const int b = bid - 8576;
        topk6_body(p.logits + (size_t)b * PROTO, p.topk + (size_t)b * KSEL);
    }
}

// ---------------- transpose-split ----------------
struct TSplit2 {
    const float* X[2];
    __nv_bfloat16* hi[2];
    __nv_bfloat16* lo[2];
};
__global__ void tsplit_kernel(TSplit2 p) {
    __shared__ float t[32][33];
    const int z = blockIdx.z;
    const float* __restrict__ X = p.X[z];
    const int tx = threadIdx.x & 31, ty = threadIdx.x >> 5;
    const int bx = blockIdx.x * 32, by = blockIdx.y * 32;
    #pragma unroll
    for (int i = 0; i < 4; i++)
        t[ty + 8 * i][tx] = X[(size_t)(by + ty + 8 * i) * DIM + bx + tx];
    __syncthreads();
    #pragma unroll
    for (int i = 0; i < 4; i++) {
        float x = t[tx][ty + 8 * i];
        __nv_bfloat16 h = __float2bfloat16(x);
        __nv_bfloat16 l = __float2bfloat16(x - __bfloat162float(h));
        size_t o = (size_t)(bx + ty + 8 * i) * DIM + by + tx;
        p.hi[z][o] = h;
        p.lo[z][o] = l;
    }
}

// ---------------- mma.sync GEMM (bf16x3), 128x64 tile, 2 CTAs/SM ----------
// 256 threads (8 warps, 4m x 2n => warp tile 32x32), 3-stage cp.async
// (R13 pipeline verbatim; only the warp partition changed).
#define BK 32
#define SKB2 80                       /* smem row stride bytes */
#define TILE_A_SM (128 * SKB2)        /* 10240 B */
#define TILE_B_SM (64 * SKB2)         /* 5120 B */
#define STAGE_SM (2 * TILE_A_SM + 2 * TILE_B_SM)   /* 30720 B */
#define MMA_SMEM (3 * STAGE_SM)       /* 92160 B -> 2 CTAs/SM */
#define NTILES (DIM / 64)             /* 16 n-tiles per row block */

struct MmaJob {
    const __nv_bfloat16 *Ahi, *Alo, *Bhi, *Blo;
    const float* bias;
    float* C;
    __nv_bfloat16 *Chi, *Clo;
    int prefix;
};
struct MmaB {
    MmaJob j[3];
    int nj;
};

__global__ __launch_bounds__(256, 2)
void mma_gemm(MmaB p) {
    extern __shared__ __align__(16) char sm[];
    const u32 sbase = smem_u32(sm);

    const int bid = blockIdx.x;
    int z = 0;
    if (p.nj > 1 && bid >= p.j[1].prefix) z = 1;
    if (p.nj > 2 && bid >= p.j[2].prefix) z = 2;
    const MmaJob& J = p.j[z];
    const int rel = bid - J.prefix;
    const int m0 = (rel / NTILES) * 128, n0 = (rel % NTILES) * 64;

    const int tid = threadIdx.x, lane = tid & 31, wid = tid >> 5;
    const int wm = wid >> 1, wn = wid & 1;   // 4m x 2n warps, 32x32 warp tile

    // A loads: 2 chunks per thread per limb (128 rows x 4 segs = 512 chunks)
    const int ar0 = tid >> 2, as0 = tid & 3;             // rows 0-63
    const int ar1 = (tid + 256) >> 2, as1 = tid & 3;     // rows 64-127
    const __nv_bfloat16* gAhi0 = J.Ahi + (size_t)(m0 + ar0) * DIM + as0 * 8;
    const __nv_bfloat16* gAhi1 = J.Ahi + (size_t)(m0 + ar1) * DIM + as1 * 8;
    const __nv_bfloat16* gAlo0 = J.Alo + (size_t)(m0 + ar0) * DIM + as0 * 8;
    const __nv_bfloat16* gAlo1 = J.Alo + (size_t)(m0 + ar1) * DIM + as1 * 8;
    const u32 dA0 = ar0 * SKB2 + as0 * 16;
    const u32 dA1 = ar1 * SKB2 + as1 * 16;

    // B loads: 1 chunk per thread per limb (64 rows x 4 segs = 256 chunks)
    const int br = tid >> 2, bs = tid & 3;
    const __nv_bfloat16* gBhi = J.Bhi + (size_t)(n0 + br) * DIM + bs * 8;
    const __nv_bfloat16* gBlo = J.Blo + (size_t)(n0 + br) * DIM + bs * 8;
    const u32 dB = br * SKB2 + bs * 16;

    auto load_stage = [&](int s) {
        const u32 st_ = sbase + (s % 3) * STAGE_SM;
        const int k0_ = s * BK;
        cp_async16(st_ + dA0,                         gAhi0 + k0_);
        cp_async16(st_ + dA1,                         gAhi1 + k0_);
        cp_async16(st_ + TILE_A_SM + dA0,             gAlo0 + k0_);
        cp_async16(st_ + TILE_A_SM + dA1,             gAlo1 + k0_);
        cp_async16(st_ + 2 * TILE_A_SM + dB,          gBhi + k0_);
        cp_async16(st_ + 2 * TILE_A_SM + TILE_B_SM + dB, gBlo + k0_);
        cp_commit();
    };

    float c[2][4][4];
    #pragma unroll
    for (int i = 0; i < 2; i++)
        #pragma unroll
        for (int j = 0; j < 4; j++)
            #pragma unroll
            for (int q = 0; q < 4; q++) c[i][j][q] = 0.0f;

    const int NS = DIM / BK;   // 32
    load_stage(0);
    load_stage(1);

    const u32 rowoff = (lane & 15) * SKB2 + (lane >> 4) * 16;

    for (int s = 0; s < NS; s++) {
        if (s + 1 < NS) cp_wait1();
        else cp_wait0();
        __syncthreads();
        if (s + 2 < NS) load_stage(s + 2);

        const u32 st = sbase + (s % 3) * STAGE_SM;
        const u32 aHiB = st + (wm * 32) * SKB2;
        const u32 aLoB = st + TILE_A_SM + (wm * 32) * SKB2;
        const u32 bHiB = st + 2 * TILE_A_SM + (wn * 32) * SKB2;
        const u32 bLoB = bHiB + TILE_B_SM;

        #pragma unroll
        for (int kk = 0; kk < 2; kk++) {
            const u32 ko = kk * 32;
            u32 ah[2][4], al[2][4];
            ldsm4(ah[0], aHiB + rowoff + ko);
            ldsm4(ah[1], aHiB + 16 * SKB2 + rowoff + ko);
            ldsm4(al[0], aLoB + rowoff + ko);
            ldsm4(al[1], aLoB + 16 * SKB2 + rowoff + ko);
            u32 bh[2][4], bl[2][4];
            ldsm4(bh[0], bHiB + rowoff + ko);
            ldsm4(bh[1], bHiB + 16 * SKB2 + rowoff + ko);
            ldsm4(bl[0], bLoB + rowoff + ko);
            ldsm4(bl[1], bLoB + 16 * SKB2 + rowoff + ko);
            #pragma unroll
            for (int mi = 0; mi < 2; mi++)
                #pragma unroll
                for (int g = 0; g < 2; g++)
                    #pragma unroll
                    for (int sub = 0; sub < 2; sub++) {
                        float* cc = c[mi][g * 2 + sub];
                        mma_bf16(cc, ah[mi], bh[g][sub], bh[g][sub + 2]);
                        mma_bf16(cc, ah[mi], bl[g][sub], bl[g][sub + 2]);
                        mma_bf16(cc, al[mi], bh[g][sub], bh[g][sub + 2]);
                    }
        }
    }

    // epilogue
    if (J.C) {
        float* __restrict__ C = J.C;
        const float* __restrict__ bias = J.bias;
        #pragma unroll
        for (int mi = 0; mi < 2; mi++) {
            const int row = m0 + wm * 32 + mi * 16 + (lane >> 2);
            #pragma unroll
            for (int ni = 0; ni < 4; ni++) {
                const int col = n0 + wn * 32 + ni * 8 + 2 * (lane & 3);
                float2 bv = bias ? *(const float2*)(bias + col)
                                 : make_float2(0.0f, 0.0f);
                const float* cc = c[mi][ni];
                *(float2*)&C[(size_t)row * DIM + col] =
                    make_float2(cc[0] + bv.x, cc[1] + bv.y);
                *(float2*)&C[(size_t)(row + 8) * DIM + col] =
                    make_float2(cc[2] + bv.x, cc[3] + bv.y);
            }
        }
    } else {
        __nv_bfloat16* __restrict__ Chi = J.Chi;
        __nv_bfloat16* __restrict__ Clo = J.Clo;
        #pragma unroll
        for (int mi = 0; mi < 2; mi++) {
            const int row = m0 + wm * 32 + mi * 16 + (lane >> 2);
            #pragma unroll
            for (int ni = 0; ni < 4; ni++) {
                const int col = n0 + wn * 32 + ni * 8 + 2 * (lane & 3);
                const float* cc = c[mi][ni];
                #pragma unroll
                for (int rr = 0; rr < 2; rr++) {
                    float x0 = cc[rr * 2], x1 = cc[rr * 2 + 1];
                    __nv_bfloat16 h0 = __float2bfloat16(x0);
                    __nv_bfloat16 h1 = __float2bfloat16(x1);
                    float l0 = x0 - __bfloat162float(h0);
                    float l1 = x1 - __bfloat162float(h1);
                    size_t o = (size_t)(row + rr * 8) * DIM + col;
                    __nv_bfloat162 hp; hp.x = h0; hp.y = h1;
                    *(u32*)&Chi[o] = *(u32*)&hp;
                    *(u32*)&Clo[o] = pack_bf16(l0, l1);
                }
            }
        }
    }
}

// ---------------- per-row attention, 256 threads ---------------------------
__global__ void attention_kernel(const float* __restrict__ qh,
                                 const float* __restrict__ Kb,
                                 const float* __restrict__ Vb,
                                 const int* __restrict__ topk,
                                 __nv_bfloat16* __restrict__ ctx_hi,
                                 __nv_bfloat16* __restrict__ ctx_lo,
                                 float* __restrict__ attn_out) {
    const int b = blockIdx.x;
    const int tid = threadIdx.x;   // 256
    __shared__ float q_s[DIM];
    __shared__ float k_s[KSEL][DIM];
    __shared__ int   idx_s[KSEL];
    __shared__ float s_s[HEADS][KSEL];

    if (tid < KSEL) idx_s[tid] = topk[(size_t)b * KSEL + tid];
    __syncthreads();

    {
        const float4* q4 = (const float4*)(qh + (size_t)b * DIM);
        float4* qs4 = (float4*)q_s;
        qs4[tid] = q4[tid];
        #pragma unroll
        for (int j = 0; j < KSEL; j++) {
            ((float4*)k_s[j])[tid] =
                ((const float4*)(Kb + (size_t)idx_s[j] * DIM))[tid];
        }
    }
    __syncthreads();

    if (tid < HEADS * KSEL) {
        int h = tid / KSEL, j = tid % KSEL;
        float dot = 0.0f;
        #pragma unroll
        for (int d = 0; d < DH; d++)
            dot = fmaf(q_s[h * DH + d], k_s[j][h * DH + d], dot);
        s_s[h][j] = dot * 0.125f;
    }
    __syncthreads();

    if (tid < HEADS) {
        int h = tid;
        float m = s_s[h][0];
        #pragma unroll
        for (int j = 1; j < KSEL; j++) m = fmaxf(m, s_s[h][j]);
        float e[KSEL], sum = 0.0f;
        #pragma unroll
        for (int j = 0; j < KSEL; j++) { e[j] = expf(s_s[h][j] - m); sum += e[j]; }
        float inv = 1.0f / sum;
        #pragma unroll
        for (int j = 0; j < KSEL; j++) s_s[h][j] = e[j] * inv;
    }
    __syncthreads();

    if (tid < KSEL) {
        float m = 0.0f;
        #pragma unroll
        for (int h = 0; h < HEADS; h++) m += s_s[h][tid];
        attn_out[(size_t)b * KSEL + tid] = m * (1.0f / HEADS);
    }

    #pragma unroll
    for (int it = 0; it < DIM / 256; it++) {
        int d = tid + it * 256;
        int h = d / DH;
        float acc = 0.0f;
        #pragma unroll
        for (int j = 0; j < KSEL; j++)
            acc = fmaf(s_s[h][j], Vb[(size_t)idx_s[j] * DIM + d], acc);
        __nv_bfloat16 hh = __float2bfloat16(acc);
        ctx_hi[(size_t)b * DIM + d] = hh;
        ctx_lo[(size_t)b * DIM + d] =
            __float2bfloat16(acc - __bfloat162float(hh));
    }
}

// ---------------- host launcher -------------------------------------------
extern "C" void kernel_launch(void* const* d_in, const int* in_sizes, int n_in,
                              void* d_out, int out_size) {
    const float* query  = (const float*)d_in[0];
    const float* bank   = (const float*)d_in[1];
    const float* logits = (const float*)d_in[2];
    const float* Wq_proj = (const float*)d_in[3];
    const float* bq_proj = (const float*)d_in[4];
    const float* Wp_proj = (const float*)d_in[5];
    const float* bp_proj = (const float*)d_in[6];
    const float* Wq = (const float*)d_in[7];
    const float* bq = (const float*)d_in[8];
    const float* Wk = (const float*)d_in[9];
    const float* bk = (const float*)d_in[10];
    const float* Wv = (const float*)d_in[11];
    const float* bv = (const float*)d_in[12];
    const float* Wo = (const float*)d_in[13];
    const float* bo = (const float*)d_in[14];

    float* out = (float*)d_out;
    float* out_ctx  = out;
    float* out_attn = out + (size_t)BATCH * DIM;

    float *bqc, *bkc, *bvc, *qh, *Kb, *Vb;
    int* topk;
    cudaGetSymbolAddress((void**)&bqc, g_bqc);
    cudaGetSymbolAddress((void**)&bkc, g_bkc);
    cudaGetSymbolAddress((void**)&bvc, g_bvc);
    cudaGetSymbolAddress((void**)&qh,  g_qh);
    cudaGetSymbolAddress((void**)&Kb,  g_Kb);
    cudaGetSymbolAddress((void**)&Vb,  g_Vb);
    cudaGetSymbolAddress((void**)&topk, g_topk);

    __nv_bfloat16 *q_hi, *q_lo, *bank_hi, *bank_lo, *ctx_hi, *ctx_lo;
    __nv_bfloat16 *Wq_hi, *Wq_lo, *Wk_hi, *Wk_lo, *Wv_hi, *Wv_lo;
    __nv_bfloat16 *WqpT_hi, *WqpT_lo, *WppT_hi, *WppT_lo;
    __nv_bfloat16 *Wqc_hi, *Wqc_lo, *Wkc_hi, *Wkc_lo, *Wvc_hi, *Wvc_lo, *Wo_hi, *Wo_lo;
    cudaGetSymbolAddress((void**)&q_hi, g_q_hi);
    cudaGetSymbolAddress((void**)&q_lo, g_q_lo);
    cudaGetSymbolAddress((void**)&bank_hi, g_bank_hi);
    cudaGetSymbolAddress((void**)&bank_lo, g_bank_lo);
    cudaGetSymbolAddress((void**)&ctx_hi, g_ctx_hi);
    cudaGetSymbolAddress((void**)&ctx_lo, g_ctx_lo);
    cudaGetSymbolAddress((void**)&Wq_hi, g_Wq_hi);
    cudaGetSymbolAddress((void**)&Wq_lo, g_Wq_lo);
    cudaGetSymbolAddress((void**)&Wk_hi, g_Wk_hi);
    cudaGetSymbolAddress((void**)&Wk_lo, g_Wk_lo);
    cudaGetSymbolAddress((void**)&Wv_hi, g_Wv_hi);
    cudaGetSymbolAddress((void**)&Wv_lo, g_Wv_lo);
    cudaGetSymbolAddress((void**)&WqpT_hi, g_WqpT_hi);
    cudaGetSymbolAddress((void**)&WqpT_lo, g_WqpT_lo);
    cudaGetSymbolAddress((void**)&WppT_hi, g_WppT_hi);
    cudaGetSymbolAddress((void**)&WppT_lo, g_WppT_lo);
    cudaGetSymbolAddress((void**)&Wqc_hi, g_Wqc_hi);
    cudaGetSymbolAddress((void**)&Wqc_lo, g_Wqc_lo);
    cudaGetSymbolAddress((void**)&Wkc_hi, g_Wkc_hi);
    cudaGetSymbolAddress((void**)&Wkc_lo, g_Wkc_lo);
    cudaGetSymbolAddress((void**)&Wvc_hi, g_Wvc_hi);
    cudaGetSymbolAddress((void**)&Wvc_lo, g_Wvc_lo);
    cudaGetSymbolAddress((void**)&Wo_hi, g_Wo_hi);
    cudaGetSymbolAddress((void**)&Wo_lo, g_Wo_lo);

    cudaFuncSetAttribute(mma_gemm,
                         cudaFuncAttributeMaxDynamicSharedMemorySize, MMA_SMEM);

    // #1 fused prep: row-splits + bias combines + topk
    {
        PrepAll s = {};
        s.X[0] = query; s.hi[0] = q_hi;    s.lo[0] = q_lo;    s.prefix[0] = 0;
        s.X[1] = bank;  s.hi[1] = bank_hi; s.lo[1] = bank_lo; s.prefix[1] = 4096;
        s.X[2] = Wo;    s.hi[2] = Wo_hi;   s.lo[2] = Wo_lo;   s.prefix[2] = 6144;
        s.X[3] = Wq;    s.hi[3] = Wq_hi;   s.lo[3] = Wq_lo;   s.prefix[3] = 6656;
        s.X[4] = Wk;    s.hi[4] = Wk_hi;   s.lo[4] = Wk_lo;   s.prefix[4] = 7168;
        s.X[5] = Wv;    s.hi[5] = Wv_hi;   s.lo[5] = Wv_lo;   s.prefix[5] = 7680;
        s.W[0] = Wq; s.bin[0] = bq_proj; s.badd[0] = bq; s.bout[0] = bqc;
        s.W[1] = Wk; s.bin[1] = bp_proj; s.badd[1] = bk; s.bout[1] = bkc;
        s.W[2] = Wv; s.bin[2] = bp_proj; s.badd[2] = bv; s.bout[2] = bvc;
        s.logits = logits; s.topk = topk;
        prep_kernel<<<16768, 256>>>(s);
    }

    // #2 transpose-splits of projection weights
    {
        TSplit2 t = {};
        t.X[0] = Wq_proj; t.X[1] = Wp_proj;
        t.hi[0] = WqpT_hi; t.hi[1] = WppT_hi;
        t.lo[0] = WqpT_lo; t.lo[1] = WppT_lo;
        tsplit_kernel<<<dim3(32, 32, 2), 256>>>(t);
    }

    // #3 weight combines (3 x 128 = 384 blocks)
    {
        MmaB mb = {};
        mb.nj = 3;
        mb.j[0] = {Wq_hi, Wq_lo, WqpT_hi, WqpT_lo, nullptr, nullptr,
                   Wqc_hi, Wqc_lo, 0};
        mb.j[1] = {Wk_hi, Wk_lo, WppT_hi, WppT_lo, nullptr, nullptr,
                   Wkc_hi, Wkc_lo, 128};
        mb.j[2] = {Wv_hi, Wv_lo, WppT_hi, WppT_lo, nullptr, nullptr,
                   Wvc_hi, Wvc_lo, 256};
        mma_gemm<<<384, 256, MMA_SMEM>>>(mb);
    }

    // #4 merged big GEMMs: qh (1024), Kb (512), Vb (512)  [ncu lands here]
    {
        MmaB mb = {};
        mb.nj = 3;
        mb.j[0] = {q_hi, q_lo, Wqc_hi, Wqc_lo, bqc, qh, nullptr, nullptr, 0};
        mb.j[1] = {bank_hi, bank_lo, Wkc_hi, Wkc_lo, bkc, Kb, nullptr, nullptr, 1024};
        mb.j[2] = {bank_hi, bank_lo, Wvc_hi, Wvc_lo, bvc, Vb, nullptr, nullptr, 1536};
        mma_gemm<<<2048, 256, MMA_SMEM>>>(mb);
    }

    // #5 attention
    attention_kernel<<<BATCH, 256>>>(qh, Kb, Vb, topk, ctx_hi, ctx_lo, out_attn);

    // #6 out projection (1024 blocks)
    {
        MmaB mb = {};
        mb.nj = 1;
        mb.j[0] = {ctx_hi, ctx_lo, Wo_hi, Wo_lo, bo, out_ctx, nullptr, nullptr, 0};
        mma_gemm<<<1024, 256, MMA_SMEM>>>(mb);
    }
}

// round 16
// speedup vs baseline: 1.1204x; 1.0925x over previous
#include <cuda_runtime.h>
#include <cuda_bf16.h>
#include <math.h>

#define BATCH 8192
#define PROTO 4096
#define DIM   1024
#define HEADS 16
#define DH    64
#define KSEL  6

typedef unsigned long long ull;
typedef unsigned int u32;

// ---------------- device scratch ----------------
__device__ float g_bqc[DIM];
__device__ float g_bkc[DIM];
__device__ float g_bvc[DIM];
__device__ float g_qh[BATCH * DIM];
__device__ float g_Kb[PROTO * DIM];
__device__ float g_Vb[PROTO * DIM];
__device__ int   g_topk[BATCH * KSEL];

__device__ __align__(16) __nv_bfloat16 g_q_hi[BATCH * DIM];
__device__ __align__(16) __nv_bfloat16 g_q_lo[BATCH * DIM];
__device__ __align__(16) __nv_bfloat16 g_bank_hi[PROTO * DIM];
__device__ __align__(16) __nv_bfloat16 g_bank_lo[PROTO * DIM];
__device__ __align__(16) __nv_bfloat16 g_ctx_hi[BATCH * DIM];
__device__ __align__(16) __nv_bfloat16 g_ctx_lo[BATCH * DIM];
__device__ __align__(16) __nv_bfloat16 g_Wq_hi[DIM * DIM];
__device__ __align__(16) __nv_bfloat16 g_Wq_lo[DIM * DIM];
__device__ __align__(16) __nv_bfloat16 g_Wk_hi[DIM * DIM];
__device__ __align__(16) __nv_bfloat16 g_Wk_lo[DIM * DIM];
__device__ __align__(16) __nv_bfloat16 g_Wv_hi[DIM * DIM];
__device__ __align__(16) __nv_bfloat16 g_Wv_lo[DIM * DIM];
__device__ __align__(16) __nv_bfloat16 g_WqpT_hi[DIM * DIM];
__device__ __align__(16) __nv_bfloat16 g_WqpT_lo[DIM * DIM];
__device__ __align__(16) __nv_bfloat16 g_WppT_hi[DIM * DIM];
__device__ __align__(16) __nv_bfloat16 g_WppT_lo[DIM * DIM];
__device__ __align__(16) __nv_bfloat16 g_Wqc_hi[DIM * DIM];
__device__ __align__(16) __nv_bfloat16 g_Wqc_lo[DIM * DIM];
__device__ __align__(16) __nv_bfloat16 g_Wkc_hi[DIM * DIM];
__device__ __align__(16) __nv_bfloat16 g_Wkc_lo[DIM * DIM];
__device__ __align__(16) __nv_bfloat16 g_Wvc_hi[DIM * DIM];
__device__ __align__(16) __nv_bfloat16 g_Wvc_lo[DIM * DIM];
__device__ __align__(16) __nv_bfloat16 g_Wo_hi[DIM * DIM];
__device__ __align__(16) __nv_bfloat16 g_Wo_lo[DIM * DIM];

// ---------------- low-level helpers ----------------
__device__ __forceinline__ u32 smem_u32(const void* p) {
    u32 a;
    asm("{ .reg .u64 t; cvta.to.shared.u64 t, %1; cvt.u32.u64 %0, t; }"
        : "=r"(a) : "l"(p));
    return a;
}
__device__ __forceinline__ void cp_async16(u32 dst, const void* src) {
    asm volatile("cp.async.cg.shared.global [%0], [%1], 16;"
                 :: "r"(dst), "l"(src) : "memory");
}
__device__ __forceinline__ void cp_commit() {
    asm volatile("cp.async.commit_group;" ::: "memory");
}
__device__ __forceinline__ void cp_wait1() {
    asm volatile("cp.async.wait_group 1;" ::: "memory");
}
__device__ __forceinline__ void cp_wait0() {
    asm volatile("cp.async.wait_group 0;" ::: "memory");
}
__device__ __forceinline__ void ldsm4(u32* d, u32 addr) {
    asm volatile("ldmatrix.sync.aligned.m8n8.x4.shared.b16 {%0,%1,%2,%3}, [%4];"
                 : "=r"(d[0]), "=r"(d[1]), "=r"(d[2]), "=r"(d[3]) : "r"(addr));
}
__device__ __forceinline__ void mma_bf16(float* c, const u32* a, u32 b0, u32 b1) {
    asm volatile("mma.sync.aligned.m16n8k16.row.col.f32.bf16.bf16.f32 "
                 "{%0,%1,%2,%3},{%4,%5,%6,%7},{%8,%9},{%0,%1,%2,%3};"
                 : "+f"(c[0]), "+f"(c[1]), "+f"(c[2]), "+f"(c[3])
                 : "r"(a[0]), "r"(a[1]), "r"(a[2]), "r"(a[3]), "r"(b0), "r"(b1));
}
__device__ __forceinline__ u32 pack_bf16(float x, float y) {
    __nv_bfloat162 p = __floats2bfloat162_rn(x, y);
    return *(u32*)&p;
}

// ---------------- fused prep: splits + bias combines + topk ---------------
struct PrepAll {
    const float* X[6];
    __nv_bfloat16* hi[6];
    __nv_bfloat16* lo[6];
    int prefix[6];
    const float* W[3];
    const float* bin[3];
    const float* badd[3];
    float* bout[3];
    const float* logits;
    int* topk;
};

__device__ __forceinline__ void topk6_body(const float* __restrict__ src,
                                           int* __restrict__ out) {
    const int tid = threadIdx.x;   // 256
    const int lane = tid & 31, wid = tid >> 5;

    float v[KSEL]; int ix[KSEL];
    #pragma unroll
    for (int q = 0; q < KSEL; q++) { v[q] = -INFINITY; ix[q] = 0x7fffffff; }

    #pragma unroll
    for (int pp = 0; pp < PROTO / 256 / 4; pp++) {
        int i = (tid + pp * 256) * 4;
        float4 x4 = *(const float4*)(src + i);
        float xs[4] = {x4.x, x4.y, x4.z, x4.w};
        #pragma unroll
        for (int u = 0; u < 4; u++) {
            float x = xs[u];
            if (x > v[KSEL - 1]) {
                v[KSEL - 1] = x; ix[KSEL - 1] = i + u;
                #pragma unroll
                for (int q = KSEL - 1; q > 0; q--) {
                    if (v[q] > v[q - 1]) {
                        float tv = v[q]; v[q] = v[q - 1]; v[q - 1] = tv;
                        int ti = ix[q]; ix[q] = ix[q - 1]; ix[q - 1] = ti;
                    }
                }
            }
        }
    }

    __shared__ float wv[8][KSEL];
    __shared__ int   wi[8][KSEL];
    #pragma unroll
    for (int t = 0; t < KSEL; t++) {
        float cv = v[0]; int ci = ix[0];
        #pragma unroll
        for (int o = 16; o; o >>= 1) {
            float ov = __shfl_down_sync(0xffffffffu, cv, o);
            int oi = __shfl_down_sync(0xffffffffu, ci, o);
            if (ov > cv || (ov == cv && oi < ci)) { cv = ov; ci = oi; }
        }
        cv = __shfl_sync(0xffffffffu, cv, 0);
        ci = __shfl_sync(0xffffffffu, ci, 0);
        if (lane == 0) { wv[wid][t] = cv; wi[wid][t] = ci; }
        if (ix[0] == ci) {
            #pragma unroll
            for (int q = 0; q < KSEL - 1; q++) { v[q] = v[q + 1]; ix[q] = ix[q + 1]; }
            v[KSEL - 1] = -INFINITY; ix[KSEL - 1] = 0x7fffffff;
        }
    }
    __syncthreads();

    if (wid == 0) {
        float lv[KSEL]; int li[KSEL];
        #pragma unroll
        for (int q = 0; q < KSEL; q++) {
            lv[q] = (lane < 8) ? wv[lane][q] : -INFINITY;
            li[q] = (lane < 8) ? wi[lane][q] : 0x7fffffff;
        }
        #pragma unroll
        for (int t = 0; t < KSEL; t++) {
            float cv = lv[0]; int ci = li[0];
            #pragma unroll
            for (int o = 16; o; o >>= 1) {
                float ov = __shfl_down_sync(0xffffffffu, cv, o);
                int oi = __shfl_down_sync(0xffffffffu, ci, o);
                if (ov > cv || (ov == cv && oi < ci)) { cv = ov; ci = oi; }
            }
            cv = __shfl_sync(0xffffffffu, cv, 0);
            ci = __shfl_sync(0xffffffffu, ci, 0);
            if (lane == 0) out[t] = ci;
            if (li[0] == ci) {
                #pragma unroll
                for (int q = 0; q < KSEL - 1; q++) { lv[q] = lv[q + 1]; li[q] = li[q + 1]; }
                lv[KSEL - 1] = -INFINITY; li[KSEL - 1] = 0x7fffffff;
            }
        }
    }
}

__global__ void prep_kernel(PrepAll p) {
    const int bid = blockIdx.x;
    if (bid < 8192) {
        int z = 0;
        #pragma unroll
        for (int q = 1; q < 6; q++) if (bid >= p.prefix[q]) z = q;
        size_t id = (((size_t)(bid - p.prefix[z])) * 256 + threadIdx.x) * 8;
        const float4* src = (const float4*)(p.X[z] + id);
        float4 a = src[0], b = src[1];
        float xs[8] = {a.x, a.y, a.z, a.w, b.x, b.y, b.z, b.w};
        __nv_bfloat16 h[8], l[8];
        #pragma unroll
        for (int i = 0; i < 8; i++) {
            h[i] = __float2bfloat16(xs[i]);
            l[i] = __float2bfloat16(xs[i] - __bfloat162float(h[i]));
        }
        *(uint4*)(p.hi[z] + id) = *(uint4*)h;
        *(uint4*)(p.lo[z] + id) = *(uint4*)l;
    } else if (bid < 8576) {
        const int r = bid - 8192;
        const int z = r >> 7;
        const int warp = threadIdx.x >> 5, lane = threadIdx.x & 31;
        const int i = (r & 127) * 8 + warp;
        const float* __restrict__ row = p.W[z] + (size_t)i * DIM;
        const float* __restrict__ bin = p.bin[z];
        float s = 0.0f;
        for (int t = lane; t < DIM; t += 32) s = fmaf(row[t], bin[t], s);
        #pragma unroll
        for (int o = 16; o; o >>= 1) s += __shfl_down_sync(0xffffffffu, s, o);
        if (lane == 0) p.bout[z][i] = s + p.badd[z][i];
    } else {
        const int b = bid - 8576;
        topk6_body(p.logits + (size_t)b * PROTO, p.topk + (size_t)b * KSEL);
    }
}

// ---------------- transpose-split ----------------
struct TSplit2 {
    const float* X[2];
    __nv_bfloat16* hi[2];
    __nv_bfloat16* lo[2];
};
__global__ void tsplit_kernel(TSplit2 p) {
    __shared__ float t[32][33];
    const int z = blockIdx.z;
    const float* __restrict__ X = p.X[z];
    const int tx = threadIdx.x & 31, ty = threadIdx.x >> 5;
    const int bx = blockIdx.x * 32, by = blockIdx.y * 32;
    #pragma unroll
    for (int i = 0; i < 4; i++)
        t[ty + 8 * i][tx] = X[(size_t)(by + ty + 8 * i) * DIM + bx + tx];
    __syncthreads();
    #pragma unroll
    for (int i = 0; i < 4; i++) {
        float x = t[tx][ty + 8 * i];
        __nv_bfloat16 h = __float2bfloat16(x);
        __nv_bfloat16 l = __float2bfloat16(x - __bfloat162float(h));
        size_t o = (size_t)(bx + ty + 8 * i) * DIM + by + tx;
        p.hi[z][o] = h;
        p.lo[z][o] = l;
    }
}

// ---------------- mma.sync GEMM (bf16x3), 128x64 tile, 2 CTAs/SM ----------
// R13 configuration verbatim: 512 threads, 16 warps 4m x 4n (32x16 warp
// tile), 3-stage cp.async, wait1.
#define BK 32
#define SKB2 80                       /* smem row stride bytes */
#define TILE_A_SM (128 * SKB2)        /* 10240 B */
#define TILE_B_SM (64 * SKB2)         /* 5120 B */
#define STAGE_SM (2 * TILE_A_SM + 2 * TILE_B_SM)   /* 30720 B */
#define MMA_SMEM (3 * STAGE_SM)       /* 92160 B -> 2 CTAs/SM */
#define NTILES (DIM / 64)             /* 16 n-tiles per row block */

struct MmaJob {
    const __nv_bfloat16 *Ahi, *Alo, *Bhi, *Blo;
    const float* bias;
    float* C;
    __nv_bfloat16 *Chi, *Clo;
    int prefix;
};
struct MmaB {
    MmaJob j[3];
    int nj;
};

__global__ __launch_bounds__(512, 2)
void mma_gemm(MmaB p) {
    extern __shared__ __align__(16) char sm[];
    const u32 sbase = smem_u32(sm);

    const int bid = blockIdx.x;
    int z = 0;
    if (p.nj > 1 && bid >= p.j[1].prefix) z = 1;
    if (p.nj > 2 && bid >= p.j[2].prefix) z = 2;
    const MmaJob& J = p.j[z];
    const int rel = bid - J.prefix;
    const int m0 = (rel / NTILES) * 128, n0 = (rel % NTILES) * 64;

    const int tid = threadIdx.x, lane = tid & 31, wid = tid >> 5;
    const int wm = wid >> 2, wn = wid & 3;   // 4x4 warps, 32x16 warp tile

    const int lrow = tid >> 2, lseg = tid & 3;
    const __nv_bfloat16* gAhi = J.Ahi + (size_t)(m0 + lrow) * DIM + lseg * 8;
    const __nv_bfloat16* gAlo = J.Alo + (size_t)(m0 + lrow) * DIM + lseg * 8;
    const u32 dA = lrow * SKB2 + lseg * 16;

    const int bt = tid & 255;
    const int brow = bt >> 2, bseg = bt & 3;
    const int limb = tid >> 8;
    const __nv_bfloat16* gB =
        (limb ? J.Blo : J.Bhi) + (size_t)(n0 + brow) * DIM + bseg * 8;
    const u32 dB = 2 * TILE_A_SM + limb * TILE_B_SM + brow * SKB2 + bseg * 16;

    auto load_stage = [&](int s) {
        const u32 st_ = sbase + (s % 3) * STAGE_SM;
        const int k0_ = s * BK;
        cp_async16(st_ + dA,             gAhi + k0_);
        cp_async16(st_ + TILE_A_SM + dA, gAlo + k0_);
        cp_async16(st_ + dB,             gB + k0_);
        cp_commit();
    };

    float c[2][2][4];
    #pragma unroll
    for (int i = 0; i < 2; i++)
        #pragma unroll
        for (int j = 0; j < 2; j++)
            #pragma unroll
            for (int q = 0; q < 4; q++) c[i][j][q] = 0.0f;

    const int NS = DIM / BK;   // 32
    load_stage(0);
    load_stage(1);

    const u32 rowoff = (lane & 15) * SKB2 + (lane >> 4) * 16;

    for (int s = 0; s < NS; s++) {
        if (s + 1 < NS) cp_wait1();
        else cp_wait0();
        __syncthreads();
        if (s + 2 < NS) load_stage(s + 2);

        const u32 st = sbase + (s % 3) * STAGE_SM;
        const u32 aHiB = st + (wm * 32) * SKB2;
        const u32 aLoB = st + TILE_A_SM + (wm * 32) * SKB2;
        const u32 bHiB = st + 2 * TILE_A_SM + (wn * 16) * SKB2;
        const u32 bLoB = bHiB + TILE_B_SM;

        #pragma unroll
        for (int kk = 0; kk < 2; kk++) {
            const u32 ko = kk * 32;
            u32 ah[2][4], al[2][4];
            ldsm4(ah[0], aHiB + rowoff + ko);
            ldsm4(ah[1], aHiB + 16 * SKB2 + rowoff + ko);
            ldsm4(al[0], aLoB + rowoff + ko);
            ldsm4(al[1], aLoB + 16 * SKB2 + rowoff + ko);
            u32 bh[4], bl[4];
            ldsm4(bh, bHiB + rowoff + ko);
            ldsm4(bl, bLoB + rowoff + ko);
            #pragma unroll
            for (int mi = 0; mi < 2; mi++)
                #pragma unroll
                for (int sub = 0; sub < 2; sub++) {
                    float* cc = c[mi][sub];
                    mma_bf16(cc, ah[mi], bh[sub], bh[sub + 2]);
                    mma_bf16(cc, ah[mi], bl[sub], bl[sub + 2]);
                    mma_bf16(cc, al[mi], bh[sub], bh[sub + 2]);
                }
        }
    }

    // epilogue
    if (J.C) {
        float* __restrict__ C = J.C;
        const float* __restrict__ bias = J.bias;
        #pragma unroll
        for (int mi = 0; mi < 2; mi++) {
            const int row = m0 + wm * 32 + mi * 16 + (lane >> 2);
            #pragma unroll
            for (int ni = 0; ni < 2; ni++) {
                const int col = n0 + wn * 16 + ni * 8 + 2 * (lane & 3);
                float2 bv = bias ? *(const float2*)(bias + col)
                                 : make_float2(0.0f, 0.0f);
                const float* cc = c[mi][ni];
                *(float2*)&C[(size_t)row * DIM + col] =
                    make_float2(cc[0] + bv.x, cc[1] + bv.y);
                *(float2*)&C[(size_t)(row + 8) * DIM + col] =
                    make_float2(cc[2] + bv.x, cc[3] + bv.y);
            }
        }
    } else {
        __nv_bfloat16* __restrict__ Chi = J.Chi;
        __nv_bfloat16* __restrict__ Clo = J.Clo;
        #pragma unroll
        for (int mi = 0; mi < 2; mi++) {
            const int row = m0 + wm * 32 + mi * 16 + (lane >> 2);
            #pragma unroll
            for (int ni = 0; ni < 2; ni++) {
                const int col = n0 + wn * 16 + ni * 8 + 2 * (lane & 3);
                const float* cc = c[mi][ni];
                #pragma unroll
                for (int rr = 0; rr < 2; rr++) {
                    float x0 = cc[rr * 2], x1 = cc[rr * 2 + 1];
                    __nv_bfloat16 h0 = __float2bfloat16(x0);
                    __nv_bfloat16 h1 = __float2bfloat16(x1);
                    float l0 = x0 - __bfloat162float(h0);
                    float l1 = x1 - __bfloat162float(h1);
                    size_t o = (size_t)(row + rr * 8) * DIM + col;
                    __nv_bfloat162 hp; hp.x = h0; hp.y = h1;
                    *(u32*)&Chi[o] = *(u32*)&hp;
                    *(u32*)&Clo[o] = pack_bf16(l0, l1);
                }
            }
        }
    }
}

// ---------------- per-row attention, 256 threads, V prefetched ------------
__global__ void attention_kernel(const float* __restrict__ qh,
                                 const float* __restrict__ Kb,
                                 const float* __restrict__ Vb,
                                 const int* __restrict__ topk,
                                 __nv_bfloat16* __restrict__ ctx_hi,
                                 __nv_bfloat16* __restrict__ ctx_lo,
                                 float* __restrict__ attn_out) {
    const int b = blockIdx.x;
    const int tid = threadIdx.x;   // 256
    __shared__ float q_s[DIM];
    __shared__ float k_s[KSEL][DIM];
    __shared__ float v_s[KSEL][DIM];
    __shared__ int   idx_s[KSEL];
    __shared__ float s_s[HEADS][KSEL];

    if (tid < KSEL) idx_s[tid] = topk[(size_t)b * KSEL + tid];
    __syncthreads();

    // load q, all K rows AND all V rows up front (V only depends on topk)
    {
        const float4* q4 = (const float4*)(qh + (size_t)b * DIM);
        ((float4*)q_s)[tid] = q4[tid];
        #pragma unroll
        for (int j = 0; j < KSEL; j++) {
            const size_t base = (size_t)idx_s[j] * DIM;
            ((float4*)k_s[j])[tid] = ((const float4*)(Kb + base))[tid];
            ((float4*)v_s[j])[tid] = ((const float4*)(Vb + base))[tid];
        }
    }
    __syncthreads();

    if (tid < HEADS * KSEL) {
        int h = tid / KSEL, j = tid % KSEL;
        float dot = 0.0f;
        #pragma unroll
        for (int d = 0; d < DH; d++)
            dot = fmaf(q_s[h * DH + d], k_s[j][h * DH + d], dot);
        s_s[h][j] = dot * 0.125f;
    }
    __syncthreads();

    if (tid < HEADS) {
        int h = tid;
        float m = s_s[h][0];
        #pragma unroll
        for (int j = 1; j < KSEL; j++) m = fmaxf(m, s_s[h][j]);
        float e[KSEL], sum = 0.0f;
        #pragma unroll
        for (int j = 0; j < KSEL; j++) { e[j] = expf(s_s[h][j] - m); sum += e[j]; }
        float inv = 1.0f / sum;
        #pragma unroll
        for (int j = 0; j < KSEL; j++) s_s[h][j] = e[j] * inv;
    }
    __syncthreads();

    if (tid < KSEL) {
        float m = 0.0f;
        #pragma unroll
        for (int h = 0; h < HEADS; h++) m += s_s[h][tid];
        attn_out[(size_t)b * KSEL + tid] = m * (1.0f / HEADS);
    }

    #pragma unroll
    for (int it = 0; it < DIM / 256; it++) {
        int d = tid + it * 256;
        int h = d / DH;
        float acc = 0.0f;
        #pragma unroll
        for (int j = 0; j < KSEL; j++)
            acc = fmaf(s_s[h][j], v_s[j][d], acc);
        __nv_bfloat16 hh = __float2bfloat16(acc);
        ctx_hi[(size_t)b * DIM + d] = hh;
        ctx_lo[(size_t)b * DIM + d] =
            __float2bfloat16(acc - __bfloat162float(hh));
    }
}

// ---------------- host launcher -------------------------------------------
extern "C" void kernel_launch(void* const* d_in, const int* in_sizes, int n_in,
                              void* d_out, int out_size) {
    const float* query  = (const float*)d_in[0];
    const float* bank   = (const float*)d_in[1];
    const float* logits = (const float*)d_in[2];
    const float* Wq_proj = (const float*)d_in[3];
    const float* bq_proj = (const float*)d_in[4];
    const float* Wp_proj = (const float*)d_in[5];
    const float* bp_proj = (const float*)d_in[6];
    const float* Wq = (const float*)d_in[7];
    const float* bq = (const float*)d_in[8];
    const float* Wk = (const float*)d_in[9];
    const float* bk = (const float*)d_in[10];
    const float* Wv = (const float*)d_in[11];
    const float* bv = (const float*)d_in[12];
    const float* Wo = (const float*)d_in[13];
    const float* bo = (const float*)d_in[14];

    float* out = (float*)d_out;
    float* out_ctx  = out;
    float* out_attn = out + (size_t)BATCH * DIM;

    float *bqc, *bkc, *bvc, *qh, *Kb, *Vb;
    int* topk;
    cudaGetSymbolAddress((void**)&bqc, g_bqc);
    cudaGetSymbolAddress((void**)&bkc, g_bkc);
    cudaGetSymbolAddress((void**)&bvc, g_bvc);
    cudaGetSymbolAddress((void**)&qh,  g_qh);
    cudaGetSymbolAddress((void**)&Kb,  g_Kb);
    cudaGetSymbolAddress((void**)&Vb,  g_Vb);
    cudaGetSymbolAddress((void**)&topk, g_topk);

    __nv_bfloat16 *q_hi, *q_lo, *bank_hi, *bank_lo, *ctx_hi, *ctx_lo;
    __nv_bfloat16 *Wq_hi, *Wq_lo, *Wk_hi, *Wk_lo, *Wv_hi, *Wv_lo;
    __nv_bfloat16 *WqpT_hi, *WqpT_lo, *WppT_hi, *WppT_lo;
    __nv_bfloat16 *Wqc_hi, *Wqc_lo, *Wkc_hi, *Wkc_lo, *Wvc_hi, *Wvc_lo, *Wo_hi, *Wo_lo;
    cudaGetSymbolAddress((void**)&q_hi, g_q_hi);
    cudaGetSymbolAddress((void**)&q_lo, g_q_lo);
    cudaGetSymbolAddress((void**)&bank_hi, g_bank_hi);
    cudaGetSymbolAddress((void**)&bank_lo, g_bank_lo);
    cudaGetSymbolAddress((void**)&ctx_hi, g_ctx_hi);
    cudaGetSymbolAddress((void**)&ctx_lo, g_ctx_lo);
    cudaGetSymbolAddress((void**)&Wq_hi, g_Wq_hi);
    cudaGetSymbolAddress((void**)&Wq_lo, g_Wq_lo);
    cudaGetSymbolAddress((void**)&Wk_hi, g_Wk_hi);
    cudaGetSymbolAddress((void**)&Wk_lo, g_Wk_lo);
    cudaGetSymbolAddress((void**)&Wv_hi, g_Wv_hi);
    cudaGetSymbolAddress((void**)&Wv_lo, g_Wv_lo);
    cudaGetSymbolAddress((void**)&WqpT_hi, g_WqpT_hi);
    cudaGetSymbolAddress((void**)&WqpT_lo, g_WqpT_lo);
    cudaGetSymbolAddress((void**)&WppT_hi, g_WppT_hi);
    cudaGetSymbolAddress((void**)&WppT_lo, g_WppT_lo);
    cudaGetSymbolAddress((void**)&Wqc_hi, g_Wqc_hi);
    cudaGetSymbolAddress((void**)&Wqc_lo, g_Wqc_lo);
    cudaGetSymbolAddress((void**)&Wkc_hi, g_Wkc_hi);
    cudaGetSymbolAddress((void**)&Wkc_lo, g_Wkc_lo);
    cudaGetSymbolAddress((void**)&Wvc_hi, g_Wvc_hi);
    cudaGetSymbolAddress((void**)&Wvc_lo, g_Wvc_lo);
    cudaGetSymbolAddress((void**)&Wo_hi, g_Wo_hi);
    cudaGetSymbolAddress((void**)&Wo_lo, g_Wo_lo);

    cudaFuncSetAttribute(mma_gemm,
                         cudaFuncAttributeMaxDynamicSharedMemorySize, MMA_SMEM);

    // #1 fused prep: row-splits + bias combines + topk
    {
        PrepAll s = {};
        s.X[0] = query; s.hi[0] = q_hi;    s.lo[0] = q_lo;    s.prefix[0] = 0;
        s.X[1] = bank;  s.hi[1] = bank_hi; s.lo[1] = bank_lo; s.prefix[1] = 4096;
        s.X[2] = Wo;    s.hi[2] = Wo_hi;   s.lo[2] = Wo_lo;   s.prefix[2] = 6144;
        s.X[3] = Wq;    s.hi[3] = Wq_hi;   s.lo[3] = Wq_lo;   s.prefix[3] = 6656;
        s.X[4] = Wk;    s.hi[4] = Wk_hi;   s.lo[4] = Wk_lo;   s.prefix[4] = 7168;
        s.X[5] = Wv;    s.hi[5] = Wv_hi;   s.lo[5] = Wv_lo;   s.prefix[5] = 7680;
        s.W[0] = Wq; s.bin[0] = bq_proj; s.badd[0] = bq; s.bout[0] = bqc;
        s.W[1] = Wk; s.bin[1] = bp_proj; s.badd[1] = bk; s.bout[1] = bkc;
        s.W[2] = Wv; s.bin[2] = bp_proj; s.badd[2] = bv; s.bout[2] = bvc;
        s.logits = logits; s.topk = topk;
        prep_kernel<<<16768, 256>>>(s);
    }

    // #2 transpose-splits of projection weights
    {
        TSplit2 t = {};
        t.X[0] = Wq_proj; t.X[1] = Wp_proj;
        t.hi[0] = WqpT_hi; t.hi[1] = WppT_hi;
        t.lo[0] = WqpT_lo; t.lo[1] = WppT_lo;
        tsplit_kernel<<<dim3(32, 32, 2), 256>>>(t);
    }

    // #3 weight combines (3 x 128 = 384 blocks)
    {
        MmaB mb = {};
        mb.nj = 3;
        mb.j[0] = {Wq_hi, Wq_lo, WqpT_hi, WqpT_lo, nullptr, nullptr,
                   Wqc_hi, Wqc_lo, 0};
        mb.j[1] = {Wk_hi, Wk_lo, WppT_hi, WppT_lo, nullptr, nullptr,
                   Wkc_hi, Wkc_lo, 128};
        mb.j[2] = {Wv_hi, Wv_lo, WppT_hi, WppT_lo, nullptr, nullptr,
                   Wvc_hi, Wvc_lo, 256};
        mma_gemm<<<384, 512, MMA_SMEM>>>(mb);
    }

    // #4 merged big GEMMs: qh (1024), Kb (512), Vb (512)  [ncu lands here]
    {
        MmaB mb = {};
        mb.nj = 3;
        mb.j[0] = {q_hi, q_lo, Wqc_hi, Wqc_lo, bqc, qh, nullptr, nullptr, 0};
        mb.j[1] = {bank_hi, bank_lo, Wkc_hi, Wkc_lo, bkc, Kb, nullptr, nullptr, 1024};
        mb.j[2] = {bank_hi, bank_lo, Wvc_hi, Wvc_lo, bvc, Vb, nullptr, nullptr, 1536};
        mma_gemm<<<2048, 512, MMA_SMEM>>>(mb);
    }

    // #5 attention (V prefetched alongside K)
    attention_kernel<<<BATCH, 256>>>(qh, Kb, Vb, topk, ctx_hi, ctx_lo, out_attn);

    // #6 out projection (1024 blocks)
    {
        MmaB mb = {};
        mb.nj = 1;
        mb.j[0] = {ctx_hi, ctx_lo, Wo_hi, Wo_lo, bo, out_ctx, nullptr, nullptr, 0};
        mma_gemm<<<1024, 512, MMA_SMEM>>>(mb);
    }
}

// round 17
// speedup vs baseline: 1.1434x; 1.0205x over previous
#include <cuda_runtime.h>
#include <cuda_bf16.h>
#include <math.h>

#define BATCH 8192
#define PROTO 4096
#define DIM   1024
#define HEADS 16
#define DH    64
#define KSEL  6

typedef unsigned long long ull;
typedef unsigned int u32;

// ---------------- device scratch ----------------
__device__ float g_bqc[DIM];
__device__ float g_bkc[DIM];
__device__ float g_bvc[DIM];
__device__ float g_qh[BATCH * DIM];
__device__ float g_Kb[PROTO * DIM];
__device__ float g_Vb[PROTO * DIM];
__device__ int   g_topk[BATCH * KSEL];

__device__ __align__(16) __nv_bfloat16 g_q_hi[BATCH * DIM];
__device__ __align__(16) __nv_bfloat16 g_q_lo[BATCH * DIM];
__device__ __align__(16) __nv_bfloat16 g_bank_hi[PROTO * DIM];
__device__ __align__(16) __nv_bfloat16 g_bank_lo[PROTO * DIM];
__device__ __align__(16) __nv_bfloat16 g_ctx_hi[BATCH * DIM];
__device__ __align__(16) __nv_bfloat16 g_ctx_lo[BATCH * DIM];
__device__ __align__(16) __nv_bfloat16 g_Wq_hi[DIM * DIM];
__device__ __align__(16) __nv_bfloat16 g_Wq_lo[DIM * DIM];
__device__ __align__(16) __nv_bfloat16 g_Wk_hi[DIM * DIM];
__device__ __align__(16) __nv_bfloat16 g_Wk_lo[DIM * DIM];
__device__ __align__(16) __nv_bfloat16 g_Wv_hi[DIM * DIM];
__device__ __align__(16) __nv_bfloat16 g_Wv_lo[DIM * DIM];
__device__ __align__(16) __nv_bfloat16 g_WqpT_hi[DIM * DIM];
__device__ __align__(16) __nv_bfloat16 g_WqpT_lo[DIM * DIM];
__device__ __align__(16) __nv_bfloat16 g_WppT_hi[DIM * DIM];
__device__ __align__(16) __nv_bfloat16 g_WppT_lo[DIM * DIM];
__device__ __align__(16) __nv_bfloat16 g_Wqc_hi[DIM * DIM];
__device__ __align__(16) __nv_bfloat16 g_Wqc_lo[DIM * DIM];
__device__ __align__(16) __nv_bfloat16 g_Wkc_hi[DIM * DIM];
__device__ __align__(16) __nv_bfloat16 g_Wkc_lo[DIM * DIM];
__device__ __align__(16) __nv_bfloat16 g_Wvc_hi[DIM * DIM];
__device__ __align__(16) __nv_bfloat16 g_Wvc_lo[DIM * DIM];
__device__ __align__(16) __nv_bfloat16 g_Wo_hi[DIM * DIM];
__device__ __align__(16) __nv_bfloat16 g_Wo_lo[DIM * DIM];

// ---------------- low-level helpers ----------------
__device__ __forceinline__ u32 smem_u32(const void* p) {
    u32 a;
    asm("{ .reg .u64 t; cvta.to.shared.u64 t, %1; cvt.u32.u64 %0, t; }"
        : "=r"(a) : "l"(p));
    return a;
}
__device__ __forceinline__ void cp_async16(u32 dst, const void* src) {
    asm volatile("cp.async.cg.shared.global [%0], [%1], 16;"
                 :: "r"(dst), "l"(src) : "memory");
}
__device__ __forceinline__ void cp_commit() {
    asm volatile("cp.async.commit_group;" ::: "memory");
}
__device__ __forceinline__ void cp_wait1() {
    asm volatile("cp.async.wait_group 1;" ::: "memory");
}
__device__ __forceinline__ void cp_wait0() {
    asm volatile("cp.async.wait_group 0;" ::: "memory");
}
__device__ __forceinline__ void ldsm4(u32* d, u32 addr) {
    asm volatile("ldmatrix.sync.aligned.m8n8.x4.shared.b16 {%0,%1,%2,%3}, [%4];"
                 : "=r"(d[0]), "=r"(d[1]), "=r"(d[2]), "=r"(d[3]) : "r"(addr));
}
__device__ __forceinline__ void mma_bf16(float* c, const u32* a, u32 b0, u32 b1) {
    asm volatile("mma.sync.aligned.m16n8k16.row.col.f32.bf16.bf16.f32 "
                 "{%0,%1,%2,%3},{%4,%5,%6,%7},{%8,%9},{%0,%1,%2,%3};"
                 : "+f"(c[0]), "+f"(c[1]), "+f"(c[2]), "+f"(c[3])
                 : "r"(a[0]), "r"(a[1]), "r"(a[2]), "r"(a[3]), "r"(b0), "r"(b1));
}
__device__ __forceinline__ u32 pack_bf16(float x, float y) {
    __nv_bfloat162 p = __floats2bfloat162_rn(x, y);
    return *(u32*)&p;
}

// ---------------- fused prep: splits + bias combines + topk ---------------
struct PrepAll {
    const float* X[6];
    __nv_bfloat16* hi[6];
    __nv_bfloat16* lo[6];
    int prefix[6];
    const float* W[3];
    const float* bin[3];
    const float* badd[3];
    float* bout[3];
    const float* logits;
    int* topk;
};

__device__ __forceinline__ void topk6_body(const float* __restrict__ src,
                                           int* __restrict__ out) {
    const int tid = threadIdx.x;   // 256
    const int lane = tid & 31, wid = tid >> 5;

    float v[KSEL]; int ix[KSEL];
    #pragma unroll
    for (int q = 0; q < KSEL; q++) { v[q] = -INFINITY; ix[q] = 0x7fffffff; }

    #pragma unroll
    for (int pp = 0; pp < PROTO / 256 / 4; pp++) {
        int i = (tid + pp * 256) * 4;
        float4 x4 = *(const float4*)(src + i);
        float xs[4] = {x4.x, x4.y, x4.z, x4.w};
        #pragma unroll
        for (int u = 0; u < 4; u++) {
            float x = xs[u];
            if (x > v[KSEL - 1]) {
                v[KSEL - 1] = x; ix[KSEL - 1] = i + u;
                #pragma unroll
                for (int q = KSEL - 1; q > 0; q--) {
                    if (v[q] > v[q - 1]) {
                        float tv = v[q]; v[q] = v[q - 1]; v[q - 1] = tv;
                        int ti = ix[q]; ix[q] = ix[q - 1]; ix[q - 1] = ti;
                    }
                }
            }
        }
    }

    __shared__ float wv[8][KSEL];
    __shared__ int   wi[8][KSEL];
    #pragma unroll
    for (int t = 0; t < KSEL; t++) {
        float cv = v[0]; int ci = ix[0];
        #pragma unroll
        for (int o = 16; o; o >>= 1) {
            float ov = __shfl_down_sync(0xffffffffu, cv, o);
            int oi = __shfl_down_sync(0xffffffffu, ci, o);
            if (ov > cv || (ov == cv && oi < ci)) { cv = ov; ci = oi; }
        }
        cv = __shfl_sync(0xffffffffu, cv, 0);
        ci = __shfl_sync(0xffffffffu, ci, 0);
        if (lane == 0) { wv[wid][t] = cv; wi[wid][t] = ci; }
        if (ix[0] == ci) {
            #pragma unroll
            for (int q = 0; q < KSEL - 1; q++) { v[q] = v[q + 1]; ix[q] = ix[q + 1]; }
            v[KSEL - 1] = -INFINITY; ix[KSEL - 1] = 0x7fffffff;
        }
    }
    __syncthreads();

    if (wid == 0) {
        float lv[KSEL]; int li[KSEL];
        #pragma unroll
        for (int q = 0; q < KSEL; q++) {
            lv[q] = (lane < 8) ? wv[lane][q] : -INFINITY;
            li[q] = (lane < 8) ? wi[lane][q] : 0x7fffffff;
        }
        #pragma unroll
        for (int t = 0; t < KSEL; t++) {
            float cv = lv[0]; int ci = li[0];
            #pragma unroll
            for (int o = 16; o; o >>= 1) {
                float ov = __shfl_down_sync(0xffffffffu, cv, o);
                int oi = __shfl_down_sync(0xffffffffu, ci, o);
                if (ov > cv || (ov == cv && oi < ci)) { cv = ov; ci = oi; }
            }
            cv = __shfl_sync(0xffffffffu, cv, 0);
            ci = __shfl_sync(0xffffffffu, ci, 0);
            if (lane == 0) out[t] = ci;
            if (li[0] == ci) {
                #pragma unroll
                for (int q = 0; q < KSEL - 1; q++) { lv[q] = lv[q + 1]; li[q] = li[q + 1]; }
                lv[KSEL - 1] = -INFINITY; li[KSEL - 1] = 0x7fffffff;
            }
        }
    }
}

__global__ void prep_kernel(PrepAll p) {
    const int bid = blockIdx.x;
    if (bid < 8192) {
        int z = 0;
        #pragma unroll
        for (int q = 1; q < 6; q++) if (bid >= p.prefix[q]) z = q;
        size_t id = (((size_t)(bid - p.prefix[z])) * 256 + threadIdx.x) * 8;
        const float4* src = (const float4*)(p.X[z] + id);
        float4 a = src[0], b = src[1];
        float xs[8] = {a.x, a.y, a.z, a.w, b.x, b.y, b.z, b.w};
        __nv_bfloat16 h[8], l[8];
        #pragma unroll
        for (int i = 0; i < 8; i++) {
            h[i] = __float2bfloat16(xs[i]);
            l[i] = __float2bfloat16(xs[i] - __bfloat162float(h[i]));
        }
        *(uint4*)(p.hi[z] + id) = *(uint4*)h;
        *(uint4*)(p.lo[z] + id) = *(uint4*)l;
    } else if (bid < 8576) {
        const int r = bid - 8192;
        const int z = r >> 7;
        const int warp = threadIdx.x >> 5, lane = threadIdx.x & 31;
        const int i = (r & 127) * 8 + warp;
        const float* __restrict__ row = p.W[z] + (size_t)i * DIM;
        const float* __restrict__ bin = p.bin[z];
        float s = 0.0f;
        for (int t = lane; t < DIM; t += 32) s = fmaf(row[t], bin[t], s);
        #pragma unroll
        for (int o = 16; o; o >>= 1) s += __shfl_down_sync(0xffffffffu, s, o);
        if (lane == 0) p.bout[z][i] = s + p.badd[z][i];
    } else {
        const int b = bid - 8576;
        topk6_body(p.logits + (size_t)b * PROTO, p.topk + (size_t)b * KSEL);
    }
}

// ---------------- transpose-split ----------------
struct TSplit2 {
    const float* X[2];
    __nv_bfloat16* hi[2];
    __nv_bfloat16* lo[2];
};
__global__ void tsplit_kernel(TSplit2 p) {
    __shared__ float t[32][33];
    const int z = blockIdx.z;
    const float* __restrict__ X = p.X[z];
    const int tx = threadIdx.x & 31, ty = threadIdx.x >> 5;
    const int bx = blockIdx.x * 32, by = blockIdx.y * 32;
    #pragma unroll
    for (int i = 0; i < 4; i++)
        t[ty + 8 * i][tx] = X[(size_t)(by + ty + 8 * i) * DIM + bx + tx];
    __syncthreads();
    #pragma unroll
    for (int i = 0; i < 4; i++) {
        float x = t[tx][ty + 8 * i];
        __nv_bfloat16 h = __float2bfloat16(x);
        __nv_bfloat16 l = __float2bfloat16(x - __bfloat162float(h));
        size_t o = (size_t)(bx + ty + 8 * i) * DIM + by + tx;
        p.hi[z][o] = h;
        p.lo[z][o] = l;
    }
}

// ---------------- mma.sync GEMM (bf16x3), 128x64 tile, 2 CTAs/SM ----------
// R13 configuration verbatim: 512 threads, 16 warps 4m x 4n (32x16 warp
// tile), 3-stage cp.async, wait1.
#define BK 32
#define SKB2 80                       /* smem row stride bytes */
#define TILE_A_SM (128 * SKB2)        /* 10240 B */
#define TILE_B_SM (64 * SKB2)         /* 5120 B */
#define STAGE_SM (2 * TILE_A_SM + 2 * TILE_B_SM)   /* 30720 B */
#define MMA_SMEM (3 * STAGE_SM)       /* 92160 B -> 2 CTAs/SM */
#define NTILES (DIM / 64)             /* 16 n-tiles per row block */

struct MmaJob {
    const __nv_bfloat16 *Ahi, *Alo, *Bhi, *Blo;
    const float* bias;
    float* C;
    __nv_bfloat16 *Chi, *Clo;
    int prefix;
};
struct MmaB {
    MmaJob j[3];
    int nj;
};

__global__ __launch_bounds__(512, 2)
void mma_gemm(MmaB p) {
    extern __shared__ __align__(16) char sm[];
    const u32 sbase = smem_u32(sm);

    const int bid = blockIdx.x;
    int z = 0;
    if (p.nj > 1 && bid >= p.j[1].prefix) z = 1;
    if (p.nj > 2 && bid >= p.j[2].prefix) z = 2;
    const MmaJob& J = p.j[z];
    const int rel = bid - J.prefix;
    const int m0 = (rel / NTILES) * 128, n0 = (rel % NTILES) * 64;

    const int tid = threadIdx.x, lane = tid & 31, wid = tid >> 5;
    const int wm = wid >> 2, wn = wid & 3;   // 4x4 warps, 32x16 warp tile

    const int lrow = tid >> 2, lseg = tid & 3;
    const __nv_bfloat16* gAhi = J.Ahi + (size_t)(m0 + lrow) * DIM + lseg * 8;
    const __nv_bfloat16* gAlo = J.Alo + (size_t)(m0 + lrow) * DIM + lseg * 8;
    const u32 dA = lrow * SKB2 + lseg * 16;

    const int bt = tid & 255;
    const int brow = bt >> 2, bseg = bt & 3;
    const int limb = tid >> 8;
    const __nv_bfloat16* gB =
        (limb ? J.Blo : J.Bhi) + (size_t)(n0 + brow) * DIM + bseg * 8;
    const u32 dB = 2 * TILE_A_SM + limb * TILE_B_SM + brow * SKB2 + bseg * 16;

    auto load_stage = [&](int s) {
        const u32 st_ = sbase + (s % 3) * STAGE_SM;
        const int k0_ = s * BK;
        cp_async16(st_ + dA,             gAhi + k0_);
        cp_async16(st_ + TILE_A_SM + dA, gAlo + k0_);
        cp_async16(st_ + dB,             gB + k0_);
        cp_commit();
    };

    float c[2][2][4];
    #pragma unroll
    for (int i = 0; i < 2; i++)
        #pragma unroll
        for (int j = 0; j < 2; j++)
            #pragma unroll
            for (int q = 0; q < 4; q++) c[i][j][q] = 0.0f;

    const int NS = DIM / BK;   // 32
    load_stage(0);
    load_stage(1);

    const u32 rowoff = (lane & 15) * SKB2 + (lane >> 4) * 16;

    for (int s = 0; s < NS; s++) {
        if (s + 1 < NS) cp_wait1();
        else cp_wait0();
        __syncthreads();
        if (s + 2 < NS) load_stage(s + 2);

        const u32 st = sbase + (s % 3) * STAGE_SM;
        const u32 aHiB = st + (wm * 32) * SKB2;
        const u32 aLoB = st + TILE_A_SM + (wm * 32) * SKB2;
        const u32 bHiB = st + 2 * TILE_A_SM + (wn * 16) * SKB2;
        const u32 bLoB = bHiB + TILE_B_SM;

        #pragma unroll
        for (int kk = 0; kk < 2; kk++) {
            const u32 ko = kk * 32;
            u32 ah[2][4], al[2][4];
            ldsm4(ah[0], aHiB + rowoff + ko);
            ldsm4(ah[1], aHiB + 16 * SKB2 + rowoff + ko);
            ldsm4(al[0], aLoB + rowoff + ko);
            ldsm4(al[1], aLoB + 16 * SKB2 + rowoff + ko);
            u32 bh[4], bl[4];
            ldsm4(bh, bHiB + rowoff + ko);
            ldsm4(bl, bLoB + rowoff + ko);
            #pragma unroll
            for (int mi = 0; mi < 2; mi++)
                #pragma unroll
                for (int sub = 0; sub < 2; sub++) {
                    float* cc = c[mi][sub];
                    mma_bf16(cc, ah[mi], bh[sub], bh[sub + 2]);
                    mma_bf16(cc, ah[mi], bl[sub], bl[sub + 2]);
                    mma_bf16(cc, al[mi], bh[sub], bh[sub + 2]);
                }
        }
    }

    // epilogue
    if (J.C) {
        float* __restrict__ C = J.C;
        const float* __restrict__ bias = J.bias;
        #pragma unroll
        for (int mi = 0; mi < 2; mi++) {
            const int row = m0 + wm * 32 + mi * 16 + (lane >> 2);
            #pragma unroll
            for (int ni = 0; ni < 2; ni++) {
                const int col = n0 + wn * 16 + ni * 8 + 2 * (lane & 3);
                float2 bv = bias ? *(const float2*)(bias + col)
                                 : make_float2(0.0f, 0.0f);
                const float* cc = c[mi][ni];
                *(float2*)&C[(size_t)row * DIM + col] =
                    make_float2(cc[0] + bv.x, cc[1] + bv.y);
                *(float2*)&C[(size_t)(row + 8) * DIM + col] =
                    make_float2(cc[2] + bv.x, cc[3] + bv.y);
            }
        }
    } else {
        __nv_bfloat16* __restrict__ Chi = J.Chi;
        __nv_bfloat16* __restrict__ Clo = J.Clo;
        #pragma unroll
        for (int mi = 0; mi < 2; mi++) {
            const int row = m0 + wm * 32 + mi * 16 + (lane >> 2);
            #pragma unroll
            for (int ni = 0; ni < 2; ni++) {
                const int col = n0 + wn * 16 + ni * 8 + 2 * (lane & 3);
                const float* cc = c[mi][ni];
                #pragma unroll
                for (int rr = 0; rr < 2; rr++) {
                    float x0 = cc[rr * 2], x1 = cc[rr * 2 + 1];
                    __nv_bfloat16 h0 = __float2bfloat16(x0);
                    __nv_bfloat16 h1 = __float2bfloat16(x1);
                    float l0 = x0 - __bfloat162float(h0);
                    float l1 = x1 - __bfloat162float(h1);
                    size_t o = (size_t)(row + rr * 8) * DIM + col;
                    __nv_bfloat162 hp; hp.x = h0; hp.y = h1;
                    *(u32*)&Chi[o] = *(u32*)&hp;
                    *(u32*)&Clo[o] = pack_bf16(l0, l1);
                }
            }
        }
    }
}

// ---------------- per-row attention, 256 threads, V in registers ----------
__global__ void attention_kernel(const float* __restrict__ qh,
                                 const float* __restrict__ Kb,
                                 const float* __restrict__ Vb,
                                 const int* __restrict__ topk,
                                 __nv_bfloat16* __restrict__ ctx_hi,
                                 __nv_bfloat16* __restrict__ ctx_lo,
                                 float* __restrict__ attn_out) {
    const int b = blockIdx.x;
    const int tid = threadIdx.x;   // 256
    __shared__ float q_s[DIM];
    __shared__ float k_s[KSEL][DIM];
    __shared__ int   idx_s[KSEL];
    __shared__ float s_s[HEADS][KSEL];

    if (tid < KSEL) idx_s[tid] = topk[(size_t)b * KSEL + tid];
    __syncthreads();

    // issue this thread's 24 V loads FIRST (registers; only depend on idx) —
    // their ~600-cycle latency overlaps q/K staging + scores + softmax
    float vreg[KSEL][DIM / 256];
    #pragma unroll
    for (int j = 0; j < KSEL; j++) {
        const float* vrow = Vb + (size_t)idx_s[j] * DIM + tid;
        #pragma unroll
        for (int it = 0; it < DIM / 256; it++)
            vreg[j][it] = __ldg(vrow + it * 256);
    }

    {
        const float4* q4 = (const float4*)(qh + (size_t)b * DIM);
        ((float4*)q_s)[tid] = q4[tid];
        #pragma unroll
        for (int j = 0; j < KSEL; j++) {
            ((float4*)k_s[j])[tid] =
                ((const float4*)(Kb + (size_t)idx_s[j] * DIM))[tid];
        }
    }
    __syncthreads();

    if (tid < HEADS * KSEL) {
        int h = tid / KSEL, j = tid % KSEL;
        float dot = 0.0f;
        #pragma unroll
        for (int d = 0; d < DH; d++)
            dot = fmaf(q_s[h * DH + d], k_s[j][h * DH + d], dot);
        s_s[h][j] = dot * 0.125f;
    }
    __syncthreads();

    if (tid < HEADS) {
        int h = tid;
        float m = s_s[h][0];
        #pragma unroll
        for (int j = 1; j < KSEL; j++) m = fmaxf(m, s_s[h][j]);
        float e[KSEL], sum = 0.0f;
        #pragma unroll
        for (int j = 0; j < KSEL; j++) { e[j] = expf(s_s[h][j] - m); sum += e[j]; }
        float inv = 1.0f / sum;
        #pragma unroll
        for (int j = 0; j < KSEL; j++) s_s[h][j] = e[j] * inv;
    }
    __syncthreads();

    if (tid < KSEL) {
        float m = 0.0f;
        #pragma unroll
        for (int h = 0; h < HEADS; h++) m += s_s[h][tid];
        attn_out[(size_t)b * KSEL + tid] = m * (1.0f / HEADS);
    }

    #pragma unroll
    for (int it = 0; it < DIM / 256; it++) {
        int d = tid + it * 256;
        int h = d / DH;
        float acc = 0.0f;
        #pragma unroll
        for (int j = 0; j < KSEL; j++)
            acc = fmaf(s_s[h][j], vreg[j][it], acc);
        __nv_bfloat16 hh = __float2bfloat16(acc);
        ctx_hi[(size_t)b * DIM + d] = hh;
        ctx_lo[(size_t)b * DIM + d] =
            __float2bfloat16(acc - __bfloat162float(hh));
    }
}

// ---------------- host launcher -------------------------------------------
extern "C" void kernel_launch(void* const* d_in, const int* in_sizes, int n_in,
                              void* d_out, int out_size) {
    const float* query  = (const float*)d_in[0];
    const float* bank   = (const float*)d_in[1];
    const float* logits = (const float*)d_in[2];
    const float* Wq_proj = (const float*)d_in[3];
    const float* bq_proj = (const float*)d_in[4];
    const float* Wp_proj = (const float*)d_in[5];
    const float* bp_proj = (const float*)d_in[6];
    const float* Wq = (const float*)d_in[7];
    const float* bq = (const float*)d_in[8];
    const float* Wk = (const float*)d_in[9];
    const float* bk = (const float*)d_in[10];
    const float* Wv = (const float*)d_in[11];
    const float* bv = (const float*)d_in[12];
    const float* Wo = (const float*)d_in[13];
    const float* bo = (const float*)d_in[14];

    float* out = (float*)d_out;
    float* out_ctx  = out;
    float* out_attn = out + (size_t)BATCH * DIM;

    float *bqc, *bkc, *bvc, *qh, *Kb, *Vb;
    int* topk;
    cudaGetSymbolAddress((void**)&bqc, g_bqc);
    cudaGetSymbolAddress((void**)&bkc, g_bkc);
    cudaGetSymbolAddress((void**)&bvc, g_bvc);
    cudaGetSymbolAddress((void**)&qh,  g_qh);
    cudaGetSymbolAddress((void**)&Kb,  g_Kb);
    cudaGetSymbolAddress((void**)&Vb,  g_Vb);
    cudaGetSymbolAddress((void**)&topk, g_topk);

    __nv_bfloat16 *q_hi, *q_lo, *bank_hi, *bank_lo, *ctx_hi, *ctx_lo;
    __nv_bfloat16 *Wq_hi, *Wq_lo, *Wk_hi, *Wk_lo, *Wv_hi, *Wv_lo;
    __nv_bfloat16 *WqpT_hi, *WqpT_lo, *WppT_hi, *WppT_lo;
    __nv_bfloat16 *Wqc_hi, *Wqc_lo, *Wkc_hi, *Wkc_lo, *Wvc_hi, *Wvc_lo, *Wo_hi, *Wo_lo;
    cudaGetSymbolAddress((void**)&q_hi, g_q_hi);
    cudaGetSymbolAddress((void**)&q_lo, g_q_lo);
    cudaGetSymbolAddress((void**)&bank_hi, g_bank_hi);
    cudaGetSymbolAddress((void**)&bank_lo, g_bank_lo);
    cudaGetSymbolAddress((void**)&ctx_hi, g_ctx_hi);
    cudaGetSymbolAddress((void**)&ctx_lo, g_ctx_lo);
    cudaGetSymbolAddress((void**)&Wq_hi, g_Wq_hi);
    cudaGetSymbolAddress((void**)&Wq_lo, g_Wq_lo);
    cudaGetSymbolAddress((void**)&Wk_hi, g_Wk_hi);
    cudaGetSymbolAddress((void**)&Wk_lo, g_Wk_lo);
    cudaGetSymbolAddress((void**)&Wv_hi, g_Wv_hi);
    cudaGetSymbolAddress((void**)&Wv_lo, g_Wv_lo);
    cudaGetSymbolAddress((void**)&WqpT_hi, g_WqpT_hi);
    cudaGetSymbolAddress((void**)&WqpT_lo, g_WqpT_lo);
    cudaGetSymbolAddress((void**)&WppT_hi, g_WppT_hi);
    cudaGetSymbolAddress((void**)&WppT_lo, g_WppT_lo);
    cudaGetSymbolAddress((void**)&Wqc_hi, g_Wqc_hi);
    cudaGetSymbolAddress((void**)&Wqc_lo, g_Wqc_lo);
    cudaGetSymbolAddress((void**)&Wkc_hi, g_Wkc_hi);
    cudaGetSymbolAddress((void**)&Wkc_lo, g_Wkc_lo);
    cudaGetSymbolAddress((void**)&Wvc_hi, g_Wvc_hi);
    cudaGetSymbolAddress((void**)&Wvc_lo, g_Wvc_lo);
    cudaGetSymbolAddress((void**)&Wo_hi, g_Wo_hi);
    cudaGetSymbolAddress((void**)&Wo_lo, g_Wo_lo);

    cudaFuncSetAttribute(mma_gemm,
                         cudaFuncAttributeMaxDynamicSharedMemorySize, MMA_SMEM);

    // #1 fused prep: row-splits + bias combines + topk
    {
        PrepAll s = {};
        s.X[0] = query; s.hi[0] = q_hi;    s.lo[0] = q_lo;    s.prefix[0] = 0;
        s.X[1] = bank;  s.hi[1] = bank_hi; s.lo[1] = bank_lo; s.prefix[1] = 4096;
        s.X[2] = Wo;    s.hi[2] = Wo_hi;   s.lo[2] = Wo_lo;   s.prefix[2] = 6144;
        s.X[3] = Wq;    s.hi[3] = Wq_hi;   s.lo[3] = Wq_lo;   s.prefix[3] = 6656;
        s.X[4] = Wk;    s.hi[4] = Wk_hi;   s.lo[4] = Wk_lo;   s.prefix[4] = 7168;
        s.X[5] = Wv;    s.hi[5] = Wv_hi;   s.lo[5] = Wv_lo;   s.prefix[5] = 7680;
        s.W[0] = Wq; s.bin[0] = bq_proj; s.badd[0] = bq; s.bout[0] = bqc;
        s.W[1] = Wk; s.bin[1] = bp_proj; s.badd[1] = bk; s.bout[1] = bkc;
        s.W[2] = Wv; s.bin[2] = bp_proj; s.badd[2] = bv; s.bout[2] = bvc;
        s.logits = logits; s.topk = topk;
        prep_kernel<<<16768, 256>>>(s);
    }

    // #2 transpose-splits of projection weights
    {
        TSplit2 t = {};
        t.X[0] = Wq_proj; t.X[1] = Wp_proj;
        t.hi[0] = WqpT_hi; t.hi[1] = WppT_hi;
        t.lo[0] = WqpT_lo; t.lo[1] = WppT_lo;
        tsplit_kernel<<<dim3(32, 32, 2), 256>>>(t);
    }

    // #3 weight combines (3 x 128 = 384 blocks)
    {
        MmaB mb = {};
        mb.nj = 3;
        mb.j[0] = {Wq_hi, Wq_lo, WqpT_hi, WqpT_lo, nullptr, nullptr,
                   Wqc_hi, Wqc_lo, 0};
        mb.j[1] = {Wk_hi, Wk_lo, WppT_hi, WppT_lo, nullptr, nullptr,
                   Wkc_hi, Wkc_lo, 128};
        mb.j[2] = {Wv_hi, Wv_lo, WppT_hi, WppT_lo, nullptr, nullptr,
                   Wvc_hi, Wvc_lo, 256};
        mma_gemm<<<384, 512, MMA_SMEM>>>(mb);
    }

    // #4 merged big GEMMs: qh (1024), Kb (512), Vb (512)  [ncu lands here]
    {
        MmaB mb = {};
        mb.nj = 3;
        mb.j[0] = {q_hi, q_lo, Wqc_hi, Wqc_lo, bqc, qh, nullptr, nullptr, 0};
        mb.j[1] = {bank_hi, bank_lo, Wkc_hi, Wkc_lo, bkc, Kb, nullptr, nullptr, 1024};
        mb.j[2] = {bank_hi, bank_lo, Wvc_hi, Wvc_lo, bvc, Vb, nullptr, nullptr, 1536};
        mma_gemm<<<2048, 512, MMA_SMEM>>>(mb);
    }

    // #5 attention (V prefetched into registers)
    attention_kernel<<<BATCH, 256>>>(qh, Kb, Vb, topk, ctx_hi, ctx_lo, out_attn);

    // #6 out projection (1024 blocks)
    {
        MmaB mb = {};
        mb.nj = 1;
        mb.j[0] = {ctx_hi, ctx_lo, Wo_hi, Wo_lo, bo, out_ctx, nullptr, nullptr, 0};
        mma_gemm<<<1024, 512, MMA_SMEM>>>(mb);
    }
}